// round 9
// baseline (speedup 1.0000x reference)
#include <cuda_runtime.h>
#include <cuda_fp16.h>
#include <cstdint>
#include <cstring>

// ---------------------------------------------------------------------------
// MultiHeadAttention B=2,S=2048,D=1024,H=16,DK=DV=64
// split-f16 mma.sync: main term fp32-accum, correction terms fp16-accum
// (2x rate hypothesis on sm_103 legacy HMMA). Low halves pre-scaled x1024.
// ---------------------------------------------------------------------------

namespace {
constexpr int  Bb = 2, S = 2048, D = 1024, H = 16;
constexpr int  M  = Bb * S;                    // 4096
constexpr float SCALE = 0.125f;
constexpr float LOSC  = 1024.0f;               // low-part pre-scale
constexpr float ILOSC = 1.0f / 1024.0f;

// projection GEMM tiling
constexpr int BM = 128, BN = 128, KCH = 32;
constexpr int NC = D / KCH;                    // 32 chunks
constexpr int ROWPAD = 40;                     // f16 elems per smem row (80 B)
constexpr int TILE_B = 128 * ROWPAD * 2;
constexpr int BUF_B  = 4 * TILE_B;
constexpr int SMEM_GEMM = 2 * BUF_B;           // 81920 B

// flash tiling
constexpr int QT = 128, KT = 64, RP = 72;
constexpr int NT = S / KT;                     // 32 kv tiles
constexpr int QBYTES  = QT * RP * 2;           // 18432
constexpr int KVBYTES = KT * RP * 2;           // 9216
constexpr int OFF_QH = 0, OFF_QL = QBYTES;
constexpr int OFF_KV = 2 * QBYTES;             // 36864
constexpr int KVBUF  = 4 * KVBYTES;            // Kh,Kl,Vh,Vl
constexpr int OFF_MK = OFF_KV + 2 * KVBUF;     // 110592
constexpr int SMEM_FLASH = OFF_MK + 128;       // 110720
}

// ---- device scratch (allocation-free). All "l" arrays hold lo*1024. ----
__device__ __half g_xh[3][(size_t)M * D];
__device__ __half g_xl[3][(size_t)M * D];
__device__ __half g_wh[4][(size_t)D * D];
__device__ __half g_wl[4][(size_t)D * D];
__device__ __half g_ah[(size_t)M * D];
__device__ __half g_al[(size_t)M * D];
__device__ __half g_qh[(size_t)Bb * H * S * 64];
__device__ __half g_ql[(size_t)Bb * H * S * 64];
__device__ __half g_kh[(size_t)Bb * H * S * 64];
__device__ __half g_kl[(size_t)Bb * H * S * 64];
__device__ __half g_vh[(size_t)Bb * H * S * 64];
__device__ __half g_vl[(size_t)Bb * H * S * 64];
__device__ unsigned char g_maskb[M];

// ---------------------------------------------------------------------------
// helpers
// ---------------------------------------------------------------------------
__device__ __forceinline__ uint32_t smem_u32(const void* p) {
    uint32_t a;
    asm("{ .reg .u64 t; cvta.to.shared.u64 t, %1; cvt.u32.u64 %0, t; }"
        : "=r"(a) : "l"(p));
    return a;
}
__device__ __forceinline__ void ldsm4(uint32_t* r, uint32_t a) {
    asm volatile("ldmatrix.sync.aligned.m8n8.x4.shared.b16 {%0,%1,%2,%3}, [%4];"
                 : "=r"(r[0]), "=r"(r[1]), "=r"(r[2]), "=r"(r[3]) : "r"(a));
}
__device__ __forceinline__ void ldsm4t(uint32_t* r, uint32_t a) {
    asm volatile("ldmatrix.sync.aligned.m8n8.x4.trans.shared.b16 {%0,%1,%2,%3}, [%4];"
                 : "=r"(r[0]), "=r"(r[1]), "=r"(r[2]), "=r"(r[3]) : "r"(a));
}
__device__ __forceinline__ uint32_t h2u(__half2 h) {
    uint32_t u;
    memcpy(&u, &h, 4);
    return u;
}
// main term: f16 inputs, fp32 accumulate
#define MMAF32(Dv, A0, A1, A2, A3, B0, B1)                                     \
    asm volatile(                                                              \
        "mma.sync.aligned.m16n8k16.row.col.f32.f16.f16.f32 "                   \
        "{%0,%1,%2,%3}, {%4,%5,%6,%7}, {%8,%9}, {%0,%1,%2,%3};"                \
        : "+f"((Dv)[0]), "+f"((Dv)[1]), "+f"((Dv)[2]), "+f"((Dv)[3])           \
        : "r"(A0), "r"(A1), "r"(A2), "r"(A3), "r"(B0), "r"(B1))
// correction terms: f16 inputs, fp16 accumulate (D = 2 packed regs)
#define MMAF16(C0, C1, A0, A1, A2, A3, B0, B1)                                 \
    asm volatile(                                                              \
        "mma.sync.aligned.m16n8k16.row.col.f16.f16.f16.f16 "                   \
        "{%0,%1}, {%2,%3,%4,%5}, {%6,%7}, {%0,%1};"                            \
        : "+r"(C0), "+r"(C1)                                                   \
        : "r"(A0), "r"(A1), "r"(A2), "r"(A3), "r"(B0), "r"(B1))
#define CPA16(dst, src)                                                        \
    asm volatile("cp.async.cg.shared.global [%0], [%1], 16;"                   \
                 :: "r"(dst), "l"(src) : "memory")

// fold fp16 correction accumulator (scaled x1024) into fp32 accumulator
__device__ __forceinline__ void fold_c(float* d, uint32_t c0, uint32_t c1) {
    __half2 h0, h1;
    memcpy(&h0, &c0, 4);
    memcpy(&h1, &c1, 4);
    d[0] += __low2float(h0)  * ILOSC;
    d[1] += __high2float(h0) * ILOSC;
    d[2] += __low2float(h1)  * ILOSC;
    d[3] += __high2float(h1) * ILOSC;
}

// ---------------------------------------------------------------------------
// Mask normalization (sniff bool/int32/float32 storage)
// ---------------------------------------------------------------------------
__global__ void mask_prepare_kernel(const unsigned char* __restrict__ raw)
{
    __shared__ int flags;
    if (threadIdx.x == 0) flags = 0;
    __syncthreads();
    int f = 0;
    for (int i = threadIdx.x; i < M; i += blockDim.x) {
        unsigned char c = raw[i];
        if ((i & 3) != 0 && c != 0) f |= 1;
        if ((i & 3) == 3 && c == 0x3F) f |= 2;
    }
    if (f) atomicOr(&flags, f);
    __syncthreads();
    const int fl = flags;
    for (int i = threadIdx.x; i < M; i += blockDim.x) {
        unsigned char v;
        if (fl & 2)      v = (((const float*)raw)[i] != 0.0f);
        else if (fl & 1) v = (raw[i] != 0);
        else             v = (((const int*)raw)[i] != 0);
        g_maskb[i] = v;
    }
}

// ---------------------------------------------------------------------------
// Fused fp32 -> f16 hi + (lo*1024) splits.
// ---------------------------------------------------------------------------
__device__ __forceinline__ void split8(const float* __restrict__ src,
                                       __half* __restrict__ hi,
                                       __half* __restrict__ lo,
                                       int i)
{
#pragma unroll
    for (int half_ = 0; half_ < 2; ++half_) {
        float4 v = *(const float4*)(src + i + half_ * 4);
        float xs[4] = {v.x, v.y, v.z, v.w};
        __half hs[4], ls[4];
#pragma unroll
        for (int j = 0; j < 4; ++j) {
            hs[j] = __float2half_rn(xs[j]);
            ls[j] = __float2half_rn((xs[j] - __half2float(hs[j])) * LOSC);
        }
        __half2 h0; h0.x = hs[0]; h0.y = hs[1];
        __half2 h1; h1.x = hs[2]; h1.y = hs[3];
        __half2 l0; l0.x = ls[0]; l0.y = ls[1];
        __half2 l1; l1.x = ls[2]; l1.y = ls[3];
        ((__half2*)(hi + i + half_ * 4))[0] = h0;
        ((__half2*)(hi + i + half_ * 4))[1] = h1;
        ((__half2*)(lo + i + half_ * 4))[0] = l0;
        ((__half2*)(lo + i + half_ * 4))[1] = l1;
    }
}

__global__ void __launch_bounds__(256) split_x_kernel(
    const float* __restrict__ q, const float* __restrict__ k,
    const float* __restrict__ v)
{
    const int z = blockIdx.z;
    const float* src = (z == 0) ? q : (z == 1 ? k : v);
    int i = (blockIdx.x * blockDim.x + threadIdx.x) * 8;
    split8(src, g_xh[z], g_xl[z], i);
}

__global__ void __launch_bounds__(256) split_w_kernel(
    const float* __restrict__ Wq, const float* __restrict__ Wk,
    const float* __restrict__ Wv, const float* __restrict__ Wo)
{
    const int z = blockIdx.z;
    const float* src = (z == 0) ? Wq : (z == 1 ? Wk : (z == 2 ? Wv : Wo));
    int i = (blockIdx.x * blockDim.x + threadIdx.x) * 8;
    split8(src, g_wh[z], g_wl[z], i);
}

// ---------------------------------------------------------------------------
// split-f16 tensor-core GEMM: acc = X@W^T (+bias).
//   main term fp32-acc, corrections (Xh*Wl' + Xl'*Wh) fp16-acc, fold /1024.
// ---------------------------------------------------------------------------
__device__ __forceinline__ void load_tile32(uint32_t sdst,
                                            const __half* __restrict__ g,
                                            int row0, int k0)
{
#pragma unroll
    for (int it = 0; it < 2; ++it) {
        int i = threadIdx.x + it * 256;
        int r = i >> 2, c = i & 3;
        uint32_t dst = sdst + (uint32_t)(r * (ROWPAD * 2) + c * 16);
        const void* src = g + (size_t)(row0 + r) * D + k0 + c * 8;
        CPA16(dst, src);
    }
}

__device__ __forceinline__ void gemm_core(
    const __half* __restrict__ Ah,
    const __half* __restrict__ Al,
    const __half* __restrict__ Bh,
    const __half* __restrict__ Bl,
    const float* __restrict__ bias,
    float* __restrict__ dst,
    __half* __restrict__ dsth,
    __half* __restrict__ dstl,
    float scale, int mode)
{
    extern __shared__ char smraw[];
    const uint32_t sb = smem_u32(smraw);

    const int tid  = threadIdx.x;
    const int lane = tid & 31;
    const int wid  = tid >> 5;
    const int mw   = wid & 1;
    const int nw   = wid >> 1;
    const int m0   = blockIdx.y * BM;
    const int n0   = blockIdx.x * BN;

    auto tile = [&](int buf, int t) -> uint32_t { return sb + buf * BUF_B + t * TILE_B; };

    const int q8   = lane >> 3;
    const int l8   = lane & 7;
    const int a_row = (q8 & 1) * 8 + l8;
    const int a_ke  = (q8 >> 1) * 8;
    const int b_row = (q8 >> 1) * 8 + l8;
    const int b_ke  = (q8 & 1) * 8;

    float d[4][4][4];
#pragma unroll
    for (int i = 0; i < 4; ++i)
#pragma unroll
        for (int j = 0; j < 4; ++j)
#pragma unroll
            for (int r = 0; r < 4; ++r) d[i][j][r] = 0.f;

#pragma unroll
    for (int p = 0; p < 2; ++p) {
        load_tile32(tile(p, 0), Ah, m0, p * KCH);
        load_tile32(tile(p, 1), Al, m0, p * KCH);
        load_tile32(tile(p, 2), Bh, n0, p * KCH);
        load_tile32(tile(p, 3), Bl, n0, p * KCH);
        asm volatile("cp.async.commit_group;" ::: "memory");
    }

    const int rq = lane >> 2;
    const int cq = (lane & 3) * 2;

    for (int c = 0; c < NC; ++c) {
        const int buf = c & 1;
        if (c == NC - 1) asm volatile("cp.async.wait_group 0;" ::: "memory");
        else             asm volatile("cp.async.wait_group 1;" ::: "memory");
        __syncthreads();

        const uint32_t xh = tile(buf, 0), xl = tile(buf, 1);
        const uint32_t wh = tile(buf, 2), wl = tile(buf, 3);

#pragma unroll
        for (int mig = 0; mig < 2; ++mig) {
            uint32_t cc[2][4][2];
#pragma unroll
            for (int mi2 = 0; mi2 < 2; ++mi2)
#pragma unroll
                for (int j = 0; j < 4; ++j) { cc[mi2][j][0] = 0; cc[mi2][j][1] = 0; }

#pragma unroll
            for (int kk2 = 0; kk2 < 2; ++kk2) {
                const int kk = kk2 * 16;
                uint32_t bhf[8], blf[8];
#pragma unroll
                for (int jp = 0; jp < 2; ++jp) {
                    int rn = nw * 32 + jp * 16 + b_row;
                    uint32_t off = (uint32_t)((rn * ROWPAD + kk + b_ke) * 2);
                    ldsm4(&bhf[jp * 4], wh + off);
                    ldsm4(&blf[jp * 4], wl + off);
                }
                uint32_t ahf[8], alf[8];
#pragma unroll
                for (int mi2 = 0; mi2 < 2; ++mi2) {
                    int rm = mw * 64 + (mig * 2 + mi2) * 16 + a_row;
                    uint32_t off = (uint32_t)((rm * ROWPAD + kk + a_ke) * 2);
                    ldsm4(&ahf[mi2 * 4], xh + off);
                    ldsm4(&alf[mi2 * 4], xl + off);
                }
                // main hh (fp32 acc)
#pragma unroll
                for (int mi2 = 0; mi2 < 2; ++mi2)
#pragma unroll
                    for (int j = 0; j < 4; ++j)
                        MMAF32(d[mig * 2 + mi2][j],
                               ahf[mi2 * 4], ahf[mi2 * 4 + 1], ahf[mi2 * 4 + 2], ahf[mi2 * 4 + 3],
                               bhf[j * 2], bhf[j * 2 + 1]);
                // corrections (fp16 acc, scaled x1024)
#pragma unroll
                for (int mi2 = 0; mi2 < 2; ++mi2)
#pragma unroll
                    for (int j = 0; j < 4; ++j)
                        MMAF16(cc[mi2][j][0], cc[mi2][j][1],
                               ahf[mi2 * 4], ahf[mi2 * 4 + 1], ahf[mi2 * 4 + 2], ahf[mi2 * 4 + 3],
                               blf[j * 2], blf[j * 2 + 1]);
#pragma unroll
                for (int mi2 = 0; mi2 < 2; ++mi2)
#pragma unroll
                    for (int j = 0; j < 4; ++j)
                        MMAF16(cc[mi2][j][0], cc[mi2][j][1],
                               alf[mi2 * 4], alf[mi2 * 4 + 1], alf[mi2 * 4 + 2], alf[mi2 * 4 + 3],
                               bhf[j * 2], bhf[j * 2 + 1]);
            }
#pragma unroll
            for (int mi2 = 0; mi2 < 2; ++mi2)
#pragma unroll
                for (int j = 0; j < 4; ++j)
                    fold_c(d[mig * 2 + mi2][j], cc[mi2][j][0], cc[mi2][j][1]);
        }
        __syncthreads();
        if (c + 2 < NC) {
            load_tile32(tile(buf, 0), Ah, m0, (c + 2) * KCH);
            load_tile32(tile(buf, 1), Al, m0, (c + 2) * KCH);
            load_tile32(tile(buf, 2), Bh, n0, (c + 2) * KCH);
            load_tile32(tile(buf, 3), Bl, n0, (c + 2) * KCH);
            asm volatile("cp.async.commit_group;" ::: "memory");
        }
    }

#pragma unroll
    for (int mi = 0; mi < 4; ++mi) {
#pragma unroll
        for (int j = 0; j < 4; ++j) {
            int r0 = m0 + mw * 64 + mi * 16 + rq;
            int n  = n0 + nw * 32 + j * 8 + cq;
            float b0 = bias[n], b1 = bias[n + 1];
#pragma unroll
            for (int h2 = 0; h2 < 2; ++h2) {
                int r = r0 + h2 * 8;
                float v0 = d[mi][j][h2 * 2 + 0] + b0;
                float v1 = d[mi][j][h2 * 2 + 1] + b1;
                if (mode == 0) {
                    float2 o; o.x = v0; o.y = v1;
                    *(float2*)(dst + (size_t)r * D + n) = o;
                } else {
                    v0 *= scale; v1 *= scale;
                    int b = r >> 11, srow = r & 2047;
                    int hh = n >> 6, dd = n & 63;
                    size_t base = (((size_t)(b * H + hh) * S + srow) << 6) + dd;
                    __half h0 = __float2half_rn(v0);
                    __half h1 = __float2half_rn(v1);
                    __half2 hp; hp.x = h0; hp.y = h1;
                    __half2 lp;
                    lp.x = __float2half_rn((v0 - __half2float(h0)) * LOSC);
                    lp.y = __float2half_rn((v1 - __half2float(h1)) * LOSC);
                    *(uint32_t*)(dsth + base) = h2u(hp);
                    *(uint32_t*)(dstl + base) = h2u(lp);
                }
            }
        }
    }
}

__global__ void __launch_bounds__(256, 2) gemm_qkv_kernel(
    const float* __restrict__ bq, const float* __restrict__ bk,
    const float* __restrict__ bv)
{
    const int z = blockIdx.z;
    const float* bias = (z == 0) ? bq : (z == 1 ? bk : bv);
    __half* dh = (z == 0) ? g_qh : (z == 1 ? g_kh : g_vh);
    __half* dl = (z == 0) ? g_ql : (z == 1 ? g_kl : g_vl);
    float scale = (z == 0) ? SCALE : 1.0f;
    gemm_core(g_xh[z], g_xl[z], g_wh[z], g_wl[z], bias,
              nullptr, dh, dl, scale, 1);
}

__global__ void __launch_bounds__(256, 2) gemm_out_kernel(
    const float* __restrict__ bo, float* __restrict__ out)
{
    gemm_core(g_ah, g_al, g_wh[3], g_wl[3], bo, out, nullptr, nullptr, 1.0f, 0);
}

// ---------------------------------------------------------------------------
// Flash attention, split-f16. Main terms fp32-acc; corrections fp16-acc.
// q-tile 128, kv-tile 64, 8 warps, 2 CTAs/SM.
// ---------------------------------------------------------------------------
__global__ void __launch_bounds__(256, 2) flash_kernel(const float* __restrict__ prev)
{
    extern __shared__ char sm[];
    const uint32_t sb = smem_u32(sm);

    const int tid  = threadIdx.x;
    const int lane = tid & 31;
    const int w    = tid >> 5;
    const int bh   = blockIdx.y;
    const int b    = bh >> 4;
    const int hq   = bh & 15;
    const int q0   = blockIdx.x * QT;
    const int rq   = lane >> 2;
    const int cq   = (lane & 3) * 2;
    const int mrow = w * 16;

    const __half* Qhg = g_qh + ((size_t)bh * S + q0) * 64;
    const __half* Qlg = g_ql + ((size_t)bh * S + q0) * 64;
    const __half* Khg = g_kh + (size_t)bh * S * 64;
    const __half* Klg = g_kl + (size_t)bh * S * 64;
    const __half* Vhg = g_vh + (size_t)bh * S * 64;
    const __half* Vlg = g_vl + (size_t)bh * S * 64;

    // Q tiles (hi/lo) -> smem
#pragma unroll
    for (int it = 0; it < 8; ++it) {
        int i = tid + it * 256;
        int arr = i >> 10, r = (i >> 3) & 127, c = i & 7;
        const __half* src = (arr ? Qlg : Qhg) + (size_t)r * 64 + c * 8;
        uint32_t dst = sb + (arr ? OFF_QL : OFF_QH) + (uint32_t)(r * (RP * 2) + c * 16);
        CPA16(dst, src);
    }

    auto load_kv = [&](int t, int buf) {
#pragma unroll
        for (int it = 0; it < 8; ++it) {
            int i = tid + it * 256;
            int arr = i >> 9, r = (i >> 3) & 63, c = i & 7;
            const __half* base = (arr == 0) ? Khg : (arr == 1) ? Klg
                               : (arr == 2) ? Vhg : Vlg;
            const __half* src = base + (size_t)(t * KT + r) * 64 + c * 8;
            uint32_t dst = sb + OFF_KV + buf * KVBUF + arr * KVBYTES
                         + (uint32_t)(r * (RP * 2) + c * 16);
            CPA16(dst, src);
        }
        if (tid < 16) {
            uint32_t mv = *(const uint32_t*)(g_maskb + b * S + t * KT + tid * 4);
            *(uint32_t*)(sm + OFF_MK + buf * 64 + tid * 4) = mv;
        }
    };

    load_kv(0, 0);
    asm volatile("cp.async.commit_group;" ::: "memory");
    load_kv(1, 1);
    asm volatile("cp.async.commit_group;" ::: "memory");

    float m_i[2] = {-3.0e38f, -3.0e38f};
    float l_i[2] = {0.f, 0.f};
    float o[8][4];
#pragma unroll
    for (int j = 0; j < 8; ++j)
#pragma unroll
        for (int r = 0; r < 4; ++r) o[j][r] = 0.f;

    const float* prow0 = prev + ((size_t)bh * S + q0 + mrow + rq) * S;
    const float* prow1 = prow0 + (size_t)8 * S;

    for (int t = 0; t < NT; ++t) {
        const int buf = t & 1;
        if (t == NT - 1) asm volatile("cp.async.wait_group 0;" ::: "memory");
        else             asm volatile("cp.async.wait_group 1;" ::: "memory");
        __syncthreads();

        const uint32_t KH = sb + OFF_KV + buf * KVBUF;
        const uint32_t KL = KH + KVBYTES;
        const uint32_t VH = KL + KVBYTES;
        const uint32_t VL = VH + KVBYTES;
        const uint32_t QH = sb + OFF_QH, QL = sb + OFF_QL;

        // --- QK^T: fp32 hh + fp16-acc corrections ---
        float s[8][4];
        uint32_t cs[8][2];
#pragma unroll
        for (int j = 0; j < 8; ++j) {
#pragma unroll
            for (int r = 0; r < 4; ++r) s[j][r] = 0.f;
            cs[j][0] = 0; cs[j][1] = 0;
        }

#pragma unroll
        for (int kc = 0; kc < 4; ++kc) {
            uint32_t aoff = (uint32_t)((mrow + (lane & 15)) * (RP * 2)
                                       + kc * 32 + (lane >> 4) * 16);
            uint32_t ah[4], al[4];
            ldsm4(ah, QH + aoff);
            ldsm4(al, QL + aoff);
#pragma unroll
            for (int jg = 0; jg < 2; ++jg) {
                uint32_t bh4[8], bl4[8];
#pragma unroll
                for (int jp2 = 0; jp2 < 2; ++jp2) {
                    int jp = jg * 2 + jp2;
                    uint32_t boff = (uint32_t)(((jp * 2 + (lane >> 4)) * 8 + (lane & 7)) * (RP * 2)
                                               + kc * 32 + ((lane >> 3) & 1) * 16);
                    ldsm4(&bh4[jp2 * 4], KH + boff);
                    ldsm4(&bl4[jp2 * 4], KL + boff);
                }
#pragma unroll
                for (int jp2 = 0; jp2 < 2; ++jp2) {
                    int j2 = (jg * 2 + jp2) * 2;
                    MMAF32(s[j2],     ah[0], ah[1], ah[2], ah[3], bh4[jp2 * 4 + 0], bh4[jp2 * 4 + 1]);
                    MMAF32(s[j2 + 1], ah[0], ah[1], ah[2], ah[3], bh4[jp2 * 4 + 2], bh4[jp2 * 4 + 3]);
                }
#pragma unroll
                for (int jp2 = 0; jp2 < 2; ++jp2) {
                    int j2 = (jg * 2 + jp2) * 2;
                    MMAF16(cs[j2][0],     cs[j2][1],     al[0], al[1], al[2], al[3],
                           bh4[jp2 * 4 + 0], bh4[jp2 * 4 + 1]);
                    MMAF16(cs[j2 + 1][0], cs[j2 + 1][1], al[0], al[1], al[2], al[3],
                           bh4[jp2 * 4 + 2], bh4[jp2 * 4 + 3]);
                }
#pragma unroll
                for (int jp2 = 0; jp2 < 2; ++jp2) {
                    int j2 = (jg * 2 + jp2) * 2;
                    MMAF16(cs[j2][0],     cs[j2][1],     ah[0], ah[1], ah[2], ah[3],
                           bl4[jp2 * 4 + 0], bl4[jp2 * 4 + 1]);
                    MMAF16(cs[j2 + 1][0], cs[j2 + 1][1], ah[0], ah[1], ah[2], ah[3],
                           bl4[jp2 * 4 + 2], bl4[jp2 * 4 + 3]);
                }
            }
        }
#pragma unroll
        for (int j = 0; j < 8; ++j) fold_c(s[j], cs[j][0], cs[j][1]);

        // --- + prev, mask ---
#pragma unroll
        for (int j = 0; j < 8; ++j) {
            const unsigned char* mkp = (const unsigned char*)(sm + OFF_MK + buf * 64 + j * 8 + cq);
            unsigned char mk0 = mkp[0], mk1 = mkp[1];
            float2 p0 = *(const float2*)(prow0 + (size_t)t * KT + j * 8 + cq);
            float2 p1 = *(const float2*)(prow1 + (size_t)t * KT + j * 8 + cq);
            s[j][0] = mk0 ? -1.0e30f : s[j][0] + p0.x;
            s[j][1] = mk1 ? -1.0e30f : s[j][1] + p0.y;
            s[j][2] = mk0 ? -1.0e30f : s[j][2] + p1.x;
            s[j][3] = mk1 ? -1.0e30f : s[j][3] + p1.y;
        }

        // --- online softmax (rows rq, rq+8) ---
#pragma unroll
        for (int r = 0; r < 2; ++r) {
            float mx = -3.0e38f;
#pragma unroll
            for (int j = 0; j < 8; ++j)
                mx = fmaxf(mx, fmaxf(s[j][2 * r], s[j][2 * r + 1]));
            mx = fmaxf(mx, __shfl_xor_sync(0xffffffffu, mx, 1));
            mx = fmaxf(mx, __shfl_xor_sync(0xffffffffu, mx, 2));
            float m_new = fmaxf(m_i[r], mx);
            float corr  = __expf(m_i[r] - m_new);
            float rs = 0.f;
#pragma unroll
            for (int j = 0; j < 8; ++j) {
                s[j][2 * r]     = __expf(s[j][2 * r]     - m_new);
                s[j][2 * r + 1] = __expf(s[j][2 * r + 1] - m_new);
                rs += s[j][2 * r] + s[j][2 * r + 1];
            }
            rs += __shfl_xor_sync(0xffffffffu, rs, 1);
            rs += __shfl_xor_sync(0xffffffffu, rs, 2);
            l_i[r] = l_i[r] * corr + rs;
            m_i[r] = m_new;
#pragma unroll
            for (int j = 0; j < 8; ++j) {
                o[j][2 * r]     *= corr;
                o[j][2 * r + 1] *= corr;
            }
        }

        // --- P@V: fp32 hh + fp16-acc corrections; P from registers ---
        uint32_t co[8][2];
#pragma unroll
        for (int j = 0; j < 8; ++j) { co[j][0] = 0; co[j][1] = 0; }

#pragma unroll
        for (int kc2 = 0; kc2 < 4; ++kc2) {
            const int j0 = 2 * kc2, j1 = j0 + 1;
            uint32_t pah[4], pal[4];
#pragma unroll
            for (int q = 0; q < 4; ++q) {
                const int jt = (q & 2) ? j1 : j0;
                const int rr = (q & 1) ? 2 : 0;
                float x = s[jt][rr], y = s[jt][rr + 1];
                __half hx = __float2half_rn(x);
                __half hy = __float2half_rn(y);
                __half2 hp; hp.x = hx; hp.y = hy;
                __half2 lp;
                lp.x = __float2half_rn((x - __half2float(hx)) * LOSC);
                lp.y = __float2half_rn((y - __half2float(hy)) * LOSC);
                pah[q] = h2u(hp);
                pal[q] = h2u(lp);
            }
#pragma unroll
            for (int jg = 0; jg < 2; ++jg) {
                uint32_t vh4[8], vl4[8];
#pragma unroll
                for (int jp2 = 0; jp2 < 2; ++jp2) {
                    int jp = jg * 2 + jp2;
                    uint32_t voff = (uint32_t)((kc2 * 16 + ((lane >> 3) & 1) * 8 + (lane & 7)) * (RP * 2)
                                               + (jp * 2 + (lane >> 4)) * 16);
                    ldsm4t(&vh4[jp2 * 4], VH + voff);
                    ldsm4t(&vl4[jp2 * 4], VL + voff);
                }
#pragma unroll
                for (int jp2 = 0; jp2 < 2; ++jp2) {
                    int j2 = (jg * 2 + jp2) * 2;
                    MMAF32(o[j2],     pah[0], pah[1], pah[2], pah[3], vh4[jp2 * 4 + 0], vh4[jp2 * 4 + 1]);
                    MMAF32(o[j2 + 1], pah[0], pah[1], pah[2], pah[3], vh4[jp2 * 4 + 2], vh4[jp2 * 4 + 3]);
                }
#pragma unroll
                for (int jp2 = 0; jp2 < 2; ++jp2) {
                    int j2 = (jg * 2 + jp2) * 2;
                    MMAF16(co[j2][0],     co[j2][1],     pal[0], pal[1], pal[2], pal[3],
                           vh4[jp2 * 4 + 0], vh4[jp2 * 4 + 1]);
                    MMAF16(co[j2 + 1][0], co[j2 + 1][1], pal[0], pal[1], pal[2], pal[3],
                           vh4[jp2 * 4 + 2], vh4[jp2 * 4 + 3]);
                }
#pragma unroll
                for (int jp2 = 0; jp2 < 2; ++jp2) {
                    int j2 = (jg * 2 + jp2) * 2;
                    MMAF16(co[j2][0],     co[j2][1],     pah[0], pah[1], pah[2], pah[3],
                           vl4[jp2 * 4 + 0], vl4[jp2 * 4 + 1]);
                    MMAF16(co[j2 + 1][0], co[j2 + 1][1], pah[0], pah[1], pah[2], pah[3],
                           vl4[jp2 * 4 + 2], vl4[jp2 * 4 + 3]);
                }
            }
        }
#pragma unroll
        for (int j = 0; j < 8; ++j) fold_c(o[j], co[j][0], co[j][1]);

        __syncthreads();
        if (t + 2 < NT) {
            load_kv(t + 2, buf);
            asm volatile("cp.async.commit_group;" ::: "memory");
        }
    }

    // --- epilogue: normalize, emit f16 hi + lo*1024 attn [b][s][H*64] ---
    const float inv0 = 1.0f / fmaxf(l_i[0], 1e-30f);
    const float inv1 = 1.0f / fmaxf(l_i[1], 1e-30f);
    const size_t row0 = (size_t)b * S + q0 + mrow + rq;
#pragma unroll
    for (int jn = 0; jn < 8; ++jn) {
        const int col = hq * 64 + jn * 8 + cq;
        float v0 = o[jn][0] * inv0, v1 = o[jn][1] * inv0;
        float v2 = o[jn][2] * inv1, v3 = o[jn][3] * inv1;

        __half h0 = __float2half_rn(v0), h1 = __float2half_rn(v1);
        __half2 hp0; hp0.x = h0; hp0.y = h1;
        __half2 lp0;
        lp0.x = __float2half_rn((v0 - __half2float(h0)) * LOSC);
        lp0.y = __float2half_rn((v1 - __half2float(h1)) * LOSC);
        *(uint32_t*)(g_ah + row0 * 1024 + col) = h2u(hp0);
        *(uint32_t*)(g_al + row0 * 1024 + col) = h2u(lp0);

        __half h2 = __float2half_rn(v2), h3 = __float2half_rn(v3);
        __half2 hp1; hp1.x = h2; hp1.y = h3;
        __half2 lp1;
        lp1.x = __float2half_rn((v2 - __half2float(h2)) * LOSC);
        lp1.y = __float2half_rn((v3 - __half2float(h3)) * LOSC);
        *(uint32_t*)(g_ah + (row0 + 8) * 1024 + col) = h2u(hp1);
        *(uint32_t*)(g_al + (row0 + 8) * 1024 + col) = h2u(lp1);
    }
}

// ---------------------------------------------------------------------------
// Inputs: 0:q 1:k 2:v 3:prev 4:mask 5:Wq 6:bq 7:Wk 8:bk 9:Wv 10:bv 11:Wo 12:bo
// ---------------------------------------------------------------------------
extern "C" void kernel_launch(void* const* d_in, const int* in_sizes, int n_in,
                              void* d_out, int out_size)
{
    (void)in_sizes; (void)n_in; (void)out_size;

    const float* q    = (const float*)d_in[0];
    const float* kk   = (const float*)d_in[1];
    const float* v    = (const float*)d_in[2];
    const float* prev = (const float*)d_in[3];
    const unsigned char* mask = (const unsigned char*)d_in[4];
    const float* Wq = (const float*)d_in[5];
    const float* bq = (const float*)d_in[6];
    const float* Wk = (const float*)d_in[7];
    const float* bk = (const float*)d_in[8];
    const float* Wv = (const float*)d_in[9];
    const float* bv = (const float*)d_in[10];
    const float* Wo = (const float*)d_in[11];
    const float* bo = (const float*)d_in[12];
    float* out = (float*)d_out;

    cudaFuncSetAttribute(gemm_qkv_kernel,
                         cudaFuncAttributeMaxDynamicSharedMemorySize, SMEM_GEMM);
    cudaFuncSetAttribute(gemm_out_kernel,
                         cudaFuncAttributeMaxDynamicSharedMemorySize, SMEM_GEMM);
    cudaFuncSetAttribute(flash_kernel,
                         cudaFuncAttributeMaxDynamicSharedMemorySize, SMEM_FLASH);

    mask_prepare_kernel<<<1, 256>>>(mask);

    const int nX = M * D, nW = D * D;
    split_x_kernel<<<dim3(nX / 8 / 256, 1, 3), 256>>>(q, kk, v);
    split_w_kernel<<<dim3(nW / 8 / 256, 1, 4), 256>>>(Wq, Wk, Wv, Wo);

    gemm_qkv_kernel<<<dim3(D / BN, M / BM, 3), 256, SMEM_GEMM>>>(bq, bk, bv);
    flash_kernel<<<dim3(S / QT, Bb * H), 256, SMEM_FLASH>>>(prev);
    gemm_out_kernel<<<dim3(D / BN, M / BM), 256, SMEM_GEMM>>>(bo, out);
}

// round 10
// speedup vs baseline: 1.0976x; 1.0976x over previous
#include <cuda_runtime.h>
#include <cuda_bf16.h>
#include <cstdint>
#include <cstring>

// ---------------------------------------------------------------------------
// MultiHeadAttention B=2,S=2048,D=1024,H=16,DK=DV=64
// split-bf16 mma.sync (3-term, fp32 acc). R10: crossbar-byte reduction —
// GEMM 2x2 warps of 64x64 tiles (dup 4x/2x -> 2x/2x); flash QT=256
// (halves K/V fragment re-read per output).
// ---------------------------------------------------------------------------

namespace {
constexpr int  Bb = 2, S = 2048, D = 1024, H = 16;
constexpr int  M  = Bb * S;                    // 4096
constexpr float SCALE = 0.125f;

// projection GEMM tiling: CTA 128x128, 128 threads, 2x2 warps of 64x64
constexpr int BM = 128, BN = 128, KCH = 32;
constexpr int NC = D / KCH;                    // 32 chunks
constexpr int ROWPAD = 40;                     // bf16 elems per smem row (80 B)
constexpr int TILE_B = 128 * ROWPAD * 2;       // 10240
constexpr int BUF_B  = 4 * TILE_B;
constexpr int SMEM_GEMM = 2 * BUF_B;           // 81920 B

// flash tiling: q-tile 256, kv-tile 64, 8 warps x 32 q-rows, 1 CTA/SM
constexpr int QT = 256, KT = 64, RP = 72;
constexpr int NT = S / KT;                     // 32 kv tiles
constexpr int QBYTES  = QT * RP * 2;           // 36864 per array
constexpr int KVBYTES = KT * RP * 2;           // 9216
constexpr int OFF_QH = 0, OFF_QL = QBYTES;
constexpr int OFF_KV = 2 * QBYTES;             // 73728
constexpr int KVBUF  = 4 * KVBYTES;            // 36864
constexpr int OFF_MK = OFF_KV + 2 * KVBUF;     // 147456
constexpr int SMEM_FLASH = OFF_MK + 128;       // 147584
}

// ---- device scratch (allocation-free) ----
__device__ __nv_bfloat16 g_xh[3][(size_t)M * D];
__device__ __nv_bfloat16 g_xl[3][(size_t)M * D];
__device__ __nv_bfloat16 g_wh[4][(size_t)D * D];
__device__ __nv_bfloat16 g_wl[4][(size_t)D * D];
__device__ __nv_bfloat16 g_ah[(size_t)M * D];
__device__ __nv_bfloat16 g_al[(size_t)M * D];
__device__ __nv_bfloat16 g_qh[(size_t)Bb * H * S * 64];
__device__ __nv_bfloat16 g_ql[(size_t)Bb * H * S * 64];
__device__ __nv_bfloat16 g_kh[(size_t)Bb * H * S * 64];
__device__ __nv_bfloat16 g_kl[(size_t)Bb * H * S * 64];
__device__ __nv_bfloat16 g_vh[(size_t)Bb * H * S * 64];
__device__ __nv_bfloat16 g_vl[(size_t)Bb * H * S * 64];
__device__ unsigned char g_maskb[M];

// ---------------------------------------------------------------------------
// helpers
// ---------------------------------------------------------------------------
__device__ __forceinline__ uint32_t smem_u32(const void* p) {
    uint32_t a;
    asm("{ .reg .u64 t; cvta.to.shared.u64 t, %1; cvt.u32.u64 %0, t; }"
        : "=r"(a) : "l"(p));
    return a;
}
__device__ __forceinline__ void ldsm4(uint32_t* r, uint32_t a) {
    asm volatile("ldmatrix.sync.aligned.m8n8.x4.shared.b16 {%0,%1,%2,%3}, [%4];"
                 : "=r"(r[0]), "=r"(r[1]), "=r"(r[2]), "=r"(r[3]) : "r"(a));
}
__device__ __forceinline__ void ldsm4t(uint32_t* r, uint32_t a) {
    asm volatile("ldmatrix.sync.aligned.m8n8.x4.trans.shared.b16 {%0,%1,%2,%3}, [%4];"
                 : "=r"(r[0]), "=r"(r[1]), "=r"(r[2]), "=r"(r[3]) : "r"(a));
}
__device__ __forceinline__ uint32_t b2u(__nv_bfloat162 h) {
    uint32_t u;
    memcpy(&u, &h, 4);
    return u;
}
#define MMA16816(Dv, A0, A1, A2, A3, B0, B1)                                   \
    asm volatile(                                                              \
        "mma.sync.aligned.m16n8k16.row.col.f32.bf16.bf16.f32 "                 \
        "{%0,%1,%2,%3}, {%4,%5,%6,%7}, {%8,%9}, {%0,%1,%2,%3};"                \
        : "+f"((Dv)[0]), "+f"((Dv)[1]), "+f"((Dv)[2]), "+f"((Dv)[3])           \
        : "r"(A0), "r"(A1), "r"(A2), "r"(A3), "r"(B0), "r"(B1))
#define CPA16(dst, src)                                                        \
    asm volatile("cp.async.cg.shared.global [%0], [%1], 16;"                   \
                 :: "r"(dst), "l"(src) : "memory")

// ---------------------------------------------------------------------------
// Mask normalization (sniff bool/int32/float32 storage)
// ---------------------------------------------------------------------------
__global__ void mask_prepare_kernel(const unsigned char* __restrict__ raw)
{
    __shared__ int flags;
    if (threadIdx.x == 0) flags = 0;
    __syncthreads();
    int f = 0;
    for (int i = threadIdx.x; i < M; i += blockDim.x) {
        unsigned char c = raw[i];
        if ((i & 3) != 0 && c != 0) f |= 1;
        if ((i & 3) == 3 && c == 0x3F) f |= 2;
    }
    if (f) atomicOr(&flags, f);
    __syncthreads();
    const int fl = flags;
    for (int i = threadIdx.x; i < M; i += blockDim.x) {
        unsigned char v;
        if (fl & 2)      v = (((const float*)raw)[i] != 0.0f);
        else if (fl & 1) v = (raw[i] != 0);
        else             v = (((const int*)raw)[i] != 0);
        g_maskb[i] = v;
    }
}

// ---------------------------------------------------------------------------
// Fused fp32 -> bf16 hi/lo splits.
// ---------------------------------------------------------------------------
__device__ __forceinline__ void split8(const float* __restrict__ src,
                                       __nv_bfloat16* __restrict__ hi,
                                       __nv_bfloat16* __restrict__ lo,
                                       int i)
{
#pragma unroll
    for (int half = 0; half < 2; ++half) {
        float4 v = *(const float4*)(src + i + half * 4);
        float xs[4] = {v.x, v.y, v.z, v.w};
        __nv_bfloat16 hs[4], ls[4];
#pragma unroll
        for (int j = 0; j < 4; ++j) {
            hs[j] = __float2bfloat16(xs[j]);
            ls[j] = __float2bfloat16(xs[j] - __bfloat162float(hs[j]));
        }
        __nv_bfloat162 h0; h0.x = hs[0]; h0.y = hs[1];
        __nv_bfloat162 h1; h1.x = hs[2]; h1.y = hs[3];
        __nv_bfloat162 l0; l0.x = ls[0]; l0.y = ls[1];
        __nv_bfloat162 l1; l1.x = ls[2]; l1.y = ls[3];
        ((__nv_bfloat162*)(hi + i + half * 4))[0] = h0;
        ((__nv_bfloat162*)(hi + i + half * 4))[1] = h1;
        ((__nv_bfloat162*)(lo + i + half * 4))[0] = l0;
        ((__nv_bfloat162*)(lo + i + half * 4))[1] = l1;
    }
}

__global__ void __launch_bounds__(256) split_x_kernel(
    const float* __restrict__ q, const float* __restrict__ k,
    const float* __restrict__ v)
{
    const int z = blockIdx.z;
    const float* src = (z == 0) ? q : (z == 1 ? k : v);
    int i = (blockIdx.x * blockDim.x + threadIdx.x) * 8;
    split8(src, g_xh[z], g_xl[z], i);
}

__global__ void __launch_bounds__(256) split_w_kernel(
    const float* __restrict__ Wq, const float* __restrict__ Wk,
    const float* __restrict__ Wv, const float* __restrict__ Wo)
{
    const int z = blockIdx.z;
    const float* src = (z == 0) ? Wq : (z == 1 ? Wk : (z == 2 ? Wv : Wo));
    int i = (blockIdx.x * blockDim.x + threadIdx.x) * 8;
    split8(src, g_wh[z], g_wl[z], i);
}

// ---------------------------------------------------------------------------
// split-bf16 GEMM, 128 threads, 2x2 warps of 64x64 tiles.
// ---------------------------------------------------------------------------
__device__ __forceinline__ void load_tile32(uint32_t sdst,
                                            const __nv_bfloat16* __restrict__ g,
                                            int row0, int k0)
{
#pragma unroll
    for (int it = 0; it < 4; ++it) {
        int i = threadIdx.x + it * 128;       // 512 chunks of 16B
        int r = i >> 2, c = i & 3;
        uint32_t dst = sdst + (uint32_t)(r * (ROWPAD * 2) + c * 16);
        const void* src = g + (size_t)(row0 + r) * D + k0 + c * 8;
        CPA16(dst, src);
    }
}

__device__ __forceinline__ void gemm_core(
    const __nv_bfloat16* __restrict__ Ah,
    const __nv_bfloat16* __restrict__ Al,
    const __nv_bfloat16* __restrict__ Bh,
    const __nv_bfloat16* __restrict__ Bl,
    const float* __restrict__ bias,
    float* __restrict__ dst,
    __nv_bfloat16* __restrict__ dsth,
    __nv_bfloat16* __restrict__ dstl,
    float scale, int mode)
{
    extern __shared__ char smraw[];
    const uint32_t sb = smem_u32(smraw);

    const int tid  = threadIdx.x;
    const int lane = tid & 31;
    const int wid  = tid >> 5;        // 0..3
    const int mw   = wid & 1;         // 2 m-warps (64 rows each)
    const int nw   = wid >> 1;        // 2 n-warps (64 cols each)
    const int m0   = blockIdx.y * BM;
    const int n0   = blockIdx.x * BN;

    auto tile = [&](int buf, int t) -> uint32_t { return sb + buf * BUF_B + t * TILE_B; };

    const int q8   = lane >> 3;
    const int l8   = lane & 7;
    const int a_row = (q8 & 1) * 8 + l8;
    const int a_ke  = (q8 >> 1) * 8;
    const int b_row = (q8 >> 1) * 8 + l8;
    const int b_ke  = (q8 & 1) * 8;

    float d[4][8][4];                 // 4 mi x 8 j accumulators
#pragma unroll
    for (int i = 0; i < 4; ++i)
#pragma unroll
        for (int j = 0; j < 8; ++j)
#pragma unroll
            for (int r = 0; r < 4; ++r) d[i][j][r] = 0.f;

#pragma unroll
    for (int p = 0; p < 2; ++p) {
        load_tile32(tile(p, 0), Ah, m0, p * KCH);
        load_tile32(tile(p, 1), Al, m0, p * KCH);
        load_tile32(tile(p, 2), Bh, n0, p * KCH);
        load_tile32(tile(p, 3), Bl, n0, p * KCH);
        asm volatile("cp.async.commit_group;" ::: "memory");
    }

    const int rq = lane >> 2;
    const int cq = (lane & 3) * 2;

    for (int c = 0; c < NC; ++c) {
        const int buf = c & 1;
        if (c == NC - 1) asm volatile("cp.async.wait_group 0;" ::: "memory");
        else             asm volatile("cp.async.wait_group 1;" ::: "memory");
        __syncthreads();

        const uint32_t xh = tile(buf, 0), xl = tile(buf, 1);
        const uint32_t wh = tile(buf, 2), wl = tile(buf, 3);

#pragma unroll
        for (int kk2 = 0; kk2 < 2; ++kk2) {
            const int kk = kk2 * 16;
            // B fragments for all 8 j tiles (both arrays)
            uint32_t bhf[16], blf[16];
#pragma unroll
            for (int jp = 0; jp < 4; ++jp) {
                int rn = nw * 64 + jp * 16 + b_row;
                uint32_t off = (uint32_t)((rn * ROWPAD + kk + b_ke) * 2);
                ldsm4(&bhf[jp * 4], wh + off);
                ldsm4(&blf[jp * 4], wl + off);
            }
#pragma unroll
            for (int mig = 0; mig < 2; ++mig) {
                uint32_t ahf[8], alf[8];
#pragma unroll
                for (int mi2 = 0; mi2 < 2; ++mi2) {
                    int rm = mw * 64 + (mig * 2 + mi2) * 16 + a_row;
                    uint32_t off = (uint32_t)((rm * ROWPAD + kk + a_ke) * 2);
                    ldsm4(&ahf[mi2 * 4], xh + off);
                    ldsm4(&alf[mi2 * 4], xl + off);
                }
                // hh
#pragma unroll
                for (int mi2 = 0; mi2 < 2; ++mi2)
#pragma unroll
                    for (int j = 0; j < 8; ++j)
                        MMA16816(d[mig * 2 + mi2][j],
                                 ahf[mi2 * 4], ahf[mi2 * 4 + 1], ahf[mi2 * 4 + 2], ahf[mi2 * 4 + 3],
                                 bhf[j * 2], bhf[j * 2 + 1]);
                // hl
#pragma unroll
                for (int mi2 = 0; mi2 < 2; ++mi2)
#pragma unroll
                    for (int j = 0; j < 8; ++j)
                        MMA16816(d[mig * 2 + mi2][j],
                                 ahf[mi2 * 4], ahf[mi2 * 4 + 1], ahf[mi2 * 4 + 2], ahf[mi2 * 4 + 3],
                                 blf[j * 2], blf[j * 2 + 1]);
                // lh
#pragma unroll
                for (int mi2 = 0; mi2 < 2; ++mi2)
#pragma unroll
                    for (int j = 0; j < 8; ++j)
                        MMA16816(d[mig * 2 + mi2][j],
                                 alf[mi2 * 4], alf[mi2 * 4 + 1], alf[mi2 * 4 + 2], alf[mi2 * 4 + 3],
                                 bhf[j * 2], bhf[j * 2 + 1]);
            }
        }
        __syncthreads();
        if (c + 2 < NC) {
            load_tile32(tile(buf, 0), Ah, m0, (c + 2) * KCH);
            load_tile32(tile(buf, 1), Al, m0, (c + 2) * KCH);
            load_tile32(tile(buf, 2), Bh, n0, (c + 2) * KCH);
            load_tile32(tile(buf, 3), Bl, n0, (c + 2) * KCH);
            asm volatile("cp.async.commit_group;" ::: "memory");
        }
    }

#pragma unroll
    for (int mi = 0; mi < 4; ++mi) {
#pragma unroll
        for (int j = 0; j < 8; ++j) {
            int r0 = m0 + mw * 64 + mi * 16 + rq;
            int n  = n0 + nw * 64 + j * 8 + cq;
            float b0 = bias[n], b1 = bias[n + 1];
#pragma unroll
            for (int h2 = 0; h2 < 2; ++h2) {
                int r = r0 + h2 * 8;
                float v0 = d[mi][j][h2 * 2 + 0] + b0;
                float v1 = d[mi][j][h2 * 2 + 1] + b1;
                if (mode == 0) {
                    float2 o; o.x = v0; o.y = v1;
                    *(float2*)(dst + (size_t)r * D + n) = o;
                } else {
                    v0 *= scale; v1 *= scale;
                    int b = r >> 11, srow = r & 2047;
                    int hh = n >> 6, dd = n & 63;
                    size_t base = (((size_t)(b * H + hh) * S + srow) << 6) + dd;
                    __nv_bfloat16 h0 = __float2bfloat16(v0);
                    __nv_bfloat16 h1 = __float2bfloat16(v1);
                    __nv_bfloat162 hp; hp.x = h0; hp.y = h1;
                    __nv_bfloat162 lp;
                    lp.x = __float2bfloat16(v0 - __bfloat162float(h0));
                    lp.y = __float2bfloat16(v1 - __bfloat162float(h1));
                    *(uint32_t*)(dsth + base) = b2u(hp);
                    *(uint32_t*)(dstl + base) = b2u(lp);
                }
            }
        }
    }
}

__global__ void __launch_bounds__(128, 2) gemm_qkv_kernel(
    const float* __restrict__ bq, const float* __restrict__ bk,
    const float* __restrict__ bv)
{
    const int z = blockIdx.z;
    const float* bias = (z == 0) ? bq : (z == 1 ? bk : bv);
    __nv_bfloat16* dh = (z == 0) ? g_qh : (z == 1 ? g_kh : g_vh);
    __nv_bfloat16* dl = (z == 0) ? g_ql : (z == 1 ? g_kl : g_vl);
    float scale = (z == 0) ? SCALE : 1.0f;
    gemm_core(g_xh[z], g_xl[z], g_wh[z], g_wl[z], bias,
              nullptr, dh, dl, scale, 1);
}

__global__ void __launch_bounds__(128, 2) gemm_out_kernel(
    const float* __restrict__ bo, float* __restrict__ out)
{
    gemm_core(g_ah, g_al, g_wh[3], g_wl[3], bo, out, nullptr, nullptr, 1.0f, 0);
}

// ---------------------------------------------------------------------------
// Flash attention: q-tile 256, kv-tile 64, 8 warps x 32 q-rows, 1 CTA/SM.
// split-bf16 3-term everywhere, fp32 accum.
// ---------------------------------------------------------------------------
__global__ void __launch_bounds__(256, 1) flash_kernel(const float* __restrict__ prev)
{
    extern __shared__ char sm[];
    const uint32_t sb = smem_u32(sm);

    const int tid  = threadIdx.x;
    const int lane = tid & 31;
    const int w    = tid >> 5;
    const int bh   = blockIdx.y;
    const int b    = bh >> 4;
    const int hq   = bh & 15;
    const int q0   = blockIdx.x * QT;
    const int rq   = lane >> 2;
    const int cq   = (lane & 3) * 2;
    const int mrow = w * 32;          // 32 q-rows per warp

    const __nv_bfloat16* Qhg = g_qh + ((size_t)bh * S + q0) * 64;
    const __nv_bfloat16* Qlg = g_ql + ((size_t)bh * S + q0) * 64;
    const __nv_bfloat16* Khg = g_kh + (size_t)bh * S * 64;
    const __nv_bfloat16* Klg = g_kl + (size_t)bh * S * 64;
    const __nv_bfloat16* Vhg = g_vh + (size_t)bh * S * 64;
    const __nv_bfloat16* Vlg = g_vl + (size_t)bh * S * 64;

    // Q tiles (hi/lo), 256 rows -> smem
#pragma unroll
    for (int it = 0; it < 16; ++it) {
        int i = tid + it * 256;                 // 4096 chunks of 16B
        int arr = i >> 11, r = (i >> 3) & 255, c = i & 7;
        const __nv_bfloat16* src = (arr ? Qlg : Qhg) + (size_t)r * 64 + c * 8;
        uint32_t dst = sb + (arr ? OFF_QL : OFF_QH) + (uint32_t)(r * (RP * 2) + c * 16);
        CPA16(dst, src);
    }

    auto load_kv = [&](int t, int buf) {
#pragma unroll
        for (int it = 0; it < 8; ++it) {
            int i = tid + it * 256;
            int arr = i >> 9, r = (i >> 3) & 63, c = i & 7;
            const __nv_bfloat16* base = (arr == 0) ? Khg : (arr == 1) ? Klg
                                      : (arr == 2) ? Vhg : Vlg;
            const __nv_bfloat16* src = base + (size_t)(t * KT + r) * 64 + c * 8;
            uint32_t dst = sb + OFF_KV + buf * KVBUF + arr * KVBYTES
                         + (uint32_t)(r * (RP * 2) + c * 16);
            CPA16(dst, src);
        }
        if (tid < 16) {
            uint32_t mv = *(const uint32_t*)(g_maskb + b * S + t * KT + tid * 4);
            *(uint32_t*)(sm + OFF_MK + buf * 64 + tid * 4) = mv;
        }
    };

    load_kv(0, 0);
    asm volatile("cp.async.commit_group;" ::: "memory");
    load_kv(1, 1);
    asm volatile("cp.async.commit_group;" ::: "memory");

    float m_i[2][2], l_i[2][2];
    float o[2][8][4];
#pragma unroll
    for (int mi = 0; mi < 2; ++mi) {
        m_i[mi][0] = -3.0e38f; m_i[mi][1] = -3.0e38f;
        l_i[mi][0] = 0.f;      l_i[mi][1] = 0.f;
#pragma unroll
        for (int j = 0; j < 8; ++j)
#pragma unroll
            for (int r = 0; r < 4; ++r) o[mi][j][r] = 0.f;
    }

    // prev row bases for the 4 rows this thread owns: [mi][half]
    const float* prow[2][2];
#pragma unroll
    for (int mi = 0; mi < 2; ++mi)
#pragma unroll
        for (int h = 0; h < 2; ++h)
            prow[mi][h] = prev + ((size_t)bh * S + q0 + mrow + mi * 16 + h * 8 + rq) * S;

    for (int t = 0; t < NT; ++t) {
        const int buf = t & 1;
        if (t == NT - 1) asm volatile("cp.async.wait_group 0;" ::: "memory");
        else             asm volatile("cp.async.wait_group 1;" ::: "memory");
        __syncthreads();

        const uint32_t KH = sb + OFF_KV + buf * KVBUF;
        const uint32_t KL = KH + KVBYTES;
        const uint32_t VH = KL + KVBYTES;
        const uint32_t VL = VH + KVBYTES;
        const uint32_t QH = sb + OFF_QH, QL = sb + OFF_QL;

        // --- QK^T: 3 terms, 2 mi x 8 j accumulators ---
        float s[2][8][4];
#pragma unroll
        for (int mi = 0; mi < 2; ++mi)
#pragma unroll
            for (int j = 0; j < 8; ++j)
#pragma unroll
                for (int r = 0; r < 4; ++r) s[mi][j][r] = 0.f;

#pragma unroll
        for (int kc = 0; kc < 4; ++kc) {
            uint32_t ah[2][4], al[2][4];
#pragma unroll
            for (int mi = 0; mi < 2; ++mi) {
                uint32_t aoff = (uint32_t)((mrow + mi * 16 + (lane & 15)) * (RP * 2)
                                           + kc * 32 + (lane >> 4) * 16);
                ldsm4(ah[mi], QH + aoff);
                ldsm4(al[mi], QL + aoff);
            }
#pragma unroll
            for (int jg = 0; jg < 2; ++jg) {
                uint32_t bh4[8], bl4[8];
#pragma unroll
                for (int jp2 = 0; jp2 < 2; ++jp2) {
                    int jp = jg * 2 + jp2;
                    uint32_t boff = (uint32_t)(((jp * 2 + (lane >> 4)) * 8 + (lane & 7)) * (RP * 2)
                                               + kc * 32 + ((lane >> 3) & 1) * 16);
                    ldsm4(&bh4[jp2 * 4], KH + boff);
                    ldsm4(&bl4[jp2 * 4], KL + boff);
                }
                // hh
#pragma unroll
                for (int mi = 0; mi < 2; ++mi)
#pragma unroll
                    for (int jp2 = 0; jp2 < 2; ++jp2) {
                        int j2 = (jg * 2 + jp2) * 2;
                        MMA16816(s[mi][j2],     ah[mi][0], ah[mi][1], ah[mi][2], ah[mi][3],
                                 bh4[jp2 * 4 + 0], bh4[jp2 * 4 + 1]);
                        MMA16816(s[mi][j2 + 1], ah[mi][0], ah[mi][1], ah[mi][2], ah[mi][3],
                                 bh4[jp2 * 4 + 2], bh4[jp2 * 4 + 3]);
                    }
                // lh
#pragma unroll
                for (int mi = 0; mi < 2; ++mi)
#pragma unroll
                    for (int jp2 = 0; jp2 < 2; ++jp2) {
                        int j2 = (jg * 2 + jp2) * 2;
                        MMA16816(s[mi][j2],     al[mi][0], al[mi][1], al[mi][2], al[mi][3],
                                 bh4[jp2 * 4 + 0], bh4[jp2 * 4 + 1]);
                        MMA16816(s[mi][j2 + 1], al[mi][0], al[mi][1], al[mi][2], al[mi][3],
                                 bh4[jp2 * 4 + 2], bh4[jp2 * 4 + 3]);
                    }
                // hl
#pragma unroll
                for (int mi = 0; mi < 2; ++mi)
#pragma unroll
                    for (int jp2 = 0; jp2 < 2; ++jp2) {
                        int j2 = (jg * 2 + jp2) * 2;
                        MMA16816(s[mi][j2],     ah[mi][0], ah[mi][1], ah[mi][2], ah[mi][3],
                                 bl4[jp2 * 4 + 0], bl4[jp2 * 4 + 1]);
                        MMA16816(s[mi][j2 + 1], ah[mi][0], ah[mi][1], ah[mi][2], ah[mi][3],
                                 bl4[jp2 * 4 + 2], bl4[jp2 * 4 + 3]);
                    }
            }
        }

        // --- + prev, mask ---
#pragma unroll
        for (int mi = 0; mi < 2; ++mi)
#pragma unroll
            for (int j = 0; j < 8; ++j) {
                const unsigned char* mkp = (const unsigned char*)(sm + OFF_MK + buf * 64 + j * 8 + cq);
                unsigned char mk0 = mkp[0], mk1 = mkp[1];
                float2 p0 = *(const float2*)(prow[mi][0] + (size_t)t * KT + j * 8 + cq);
                float2 p1 = *(const float2*)(prow[mi][1] + (size_t)t * KT + j * 8 + cq);
                s[mi][j][0] = mk0 ? -1.0e30f : s[mi][j][0] + p0.x;
                s[mi][j][1] = mk1 ? -1.0e30f : s[mi][j][1] + p0.y;
                s[mi][j][2] = mk0 ? -1.0e30f : s[mi][j][2] + p1.x;
                s[mi][j][3] = mk1 ? -1.0e30f : s[mi][j][3] + p1.y;
            }

        // --- online softmax (4 rows per thread) ---
#pragma unroll
        for (int mi = 0; mi < 2; ++mi)
#pragma unroll
            for (int r = 0; r < 2; ++r) {
                float mx = -3.0e38f;
#pragma unroll
                for (int j = 0; j < 8; ++j)
                    mx = fmaxf(mx, fmaxf(s[mi][j][2 * r], s[mi][j][2 * r + 1]));
                mx = fmaxf(mx, __shfl_xor_sync(0xffffffffu, mx, 1));
                mx = fmaxf(mx, __shfl_xor_sync(0xffffffffu, mx, 2));
                float m_new = fmaxf(m_i[mi][r], mx);
                float corr  = __expf(m_i[mi][r] - m_new);
                float rs = 0.f;
#pragma unroll
                for (int j = 0; j < 8; ++j) {
                    s[mi][j][2 * r]     = __expf(s[mi][j][2 * r]     - m_new);
                    s[mi][j][2 * r + 1] = __expf(s[mi][j][2 * r + 1] - m_new);
                    rs += s[mi][j][2 * r] + s[mi][j][2 * r + 1];
                }
                rs += __shfl_xor_sync(0xffffffffu, rs, 1);
                rs += __shfl_xor_sync(0xffffffffu, rs, 2);
                l_i[mi][r] = l_i[mi][r] * corr + rs;
                m_i[mi][r] = m_new;
#pragma unroll
                for (int j = 0; j < 8; ++j) {
                    o[mi][j][2 * r]     *= corr;
                    o[mi][j][2 * r + 1] *= corr;
                }
            }

        // --- P@V: 3 terms, P from registers ---
#pragma unroll
        for (int kc2 = 0; kc2 < 4; ++kc2) {
            const int j0 = 2 * kc2, j1 = j0 + 1;
            uint32_t pah[2][4], pal[2][4];
#pragma unroll
            for (int mi = 0; mi < 2; ++mi)
#pragma unroll
                for (int q = 0; q < 4; ++q) {
                    const int jt = (q & 2) ? j1 : j0;
                    const int rr = (q & 1) ? 2 : 0;
                    float x = s[mi][jt][rr], y = s[mi][jt][rr + 1];
                    __nv_bfloat16 hx = __float2bfloat16(x);
                    __nv_bfloat16 hy = __float2bfloat16(y);
                    __nv_bfloat162 hp; hp.x = hx; hp.y = hy;
                    __nv_bfloat162 lp;
                    lp.x = __float2bfloat16(x - __bfloat162float(hx));
                    lp.y = __float2bfloat16(y - __bfloat162float(hy));
                    pah[mi][q] = b2u(hp);
                    pal[mi][q] = b2u(lp);
                }
#pragma unroll
            for (int jg = 0; jg < 2; ++jg) {
                uint32_t vh4[8], vl4[8];
#pragma unroll
                for (int jp2 = 0; jp2 < 2; ++jp2) {
                    int jp = jg * 2 + jp2;
                    uint32_t voff = (uint32_t)((kc2 * 16 + ((lane >> 3) & 1) * 8 + (lane & 7)) * (RP * 2)
                                               + (jp * 2 + (lane >> 4)) * 16);
                    ldsm4t(&vh4[jp2 * 4], VH + voff);
                    ldsm4t(&vl4[jp2 * 4], VL + voff);
                }
                // hh
#pragma unroll
                for (int mi = 0; mi < 2; ++mi)
#pragma unroll
                    for (int jp2 = 0; jp2 < 2; ++jp2) {
                        int j2 = (jg * 2 + jp2) * 2;
                        MMA16816(o[mi][j2],     pah[mi][0], pah[mi][1], pah[mi][2], pah[mi][3],
                                 vh4[jp2 * 4 + 0], vh4[jp2 * 4 + 1]);
                        MMA16816(o[mi][j2 + 1], pah[mi][0], pah[mi][1], pah[mi][2], pah[mi][3],
                                 vh4[jp2 * 4 + 2], vh4[jp2 * 4 + 3]);
                    }
                // lh
#pragma unroll
                for (int mi = 0; mi < 2; ++mi)
#pragma unroll
                    for (int jp2 = 0; jp2 < 2; ++jp2) {
                        int j2 = (jg * 2 + jp2) * 2;
                        MMA16816(o[mi][j2],     pal[mi][0], pal[mi][1], pal[mi][2], pal[mi][3],
                                 vh4[jp2 * 4 + 0], vh4[jp2 * 4 + 1]);
                        MMA16816(o[mi][j2 + 1], pal[mi][0], pal[mi][1], pal[mi][2], pal[mi][3],
                                 vh4[jp2 * 4 + 2], vh4[jp2 * 4 + 3]);
                    }
                // hl
#pragma unroll
                for (int mi = 0; mi < 2; ++mi)
#pragma unroll
                    for (int jp2 = 0; jp2 < 2; ++jp2) {
                        int j2 = (jg * 2 + jp2) * 2;
                        MMA16816(o[mi][j2],     pah[mi][0], pah[mi][1], pah[mi][2], pah[mi][3],
                                 vl4[jp2 * 4 + 0], vl4[jp2 * 4 + 1]);
                        MMA16816(o[mi][j2 + 1], pah[mi][0], pah[mi][1], pah[mi][2], pah[mi][3],
                                 vl4[jp2 * 4 + 2], vl4[jp2 * 4 + 3]);
                    }
            }
        }

        __syncthreads();
        if (t + 2 < NT) {
            load_kv(t + 2, buf);
            asm volatile("cp.async.commit_group;" ::: "memory");
        }
    }

    // --- epilogue: normalize, emit bf16 hi/lo attn [b][s][H*64] ---
#pragma unroll
    for (int mi = 0; mi < 2; ++mi) {
        const float inv0 = 1.0f / fmaxf(l_i[mi][0], 1e-30f);
        const float inv1 = 1.0f / fmaxf(l_i[mi][1], 1e-30f);
        const size_t row0 = (size_t)b * S + q0 + mrow + mi * 16 + rq;
#pragma unroll
        for (int jn = 0; jn < 8; ++jn) {
            const int col = hq * 64 + jn * 8 + cq;
            float v0 = o[mi][jn][0] * inv0, v1 = o[mi][jn][1] * inv0;
            float v2 = o[mi][jn][2] * inv1, v3 = o[mi][jn][3] * inv1;

            __nv_bfloat16 h0 = __float2bfloat16(v0), h1 = __float2bfloat16(v1);
            __nv_bfloat162 hp0; hp0.x = h0; hp0.y = h1;
            __nv_bfloat162 lp0;
            lp0.x = __float2bfloat16(v0 - __bfloat162float(h0));
            lp0.y = __float2bfloat16(v1 - __bfloat162float(h1));
            *(uint32_t*)(g_ah + row0 * 1024 + col) = b2u(hp0);
            *(uint32_t*)(g_al + row0 * 1024 + col) = b2u(lp0);

            __nv_bfloat16 h2 = __float2bfloat16(v2), h3 = __float2bfloat16(v3);
            __nv_bfloat162 hp1; hp1.x = h2; hp1.y = h3;
            __nv_bfloat162 lp1;
            lp1.x = __float2bfloat16(v2 - __bfloat162float(h2));
            lp1.y = __float2bfloat16(v3 - __bfloat162float(h3));
            *(uint32_t*)(g_ah + (row0 + 8) * 1024 + col) = b2u(hp1);
            *(uint32_t*)(g_al + (row0 + 8) * 1024 + col) = b2u(lp1);
        }
    }
}

// ---------------------------------------------------------------------------
// Inputs: 0:q 1:k 2:v 3:prev 4:mask 5:Wq 6:bq 7:Wk 8:bk 9:Wv 10:bv 11:Wo 12:bo
// ---------------------------------------------------------------------------
extern "C" void kernel_launch(void* const* d_in, const int* in_sizes, int n_in,
                              void* d_out, int out_size)
{
    (void)in_sizes; (void)n_in; (void)out_size;

    const float* q    = (const float*)d_in[0];
    const float* kk   = (const float*)d_in[1];
    const float* v    = (const float*)d_in[2];
    const float* prev = (const float*)d_in[3];
    const unsigned char* mask = (const unsigned char*)d_in[4];
    const float* Wq = (const float*)d_in[5];
    const float* bq = (const float*)d_in[6];
    const float* Wk = (const float*)d_in[7];
    const float* bk = (const float*)d_in[8];
    const float* Wv = (const float*)d_in[9];
    const float* bv = (const float*)d_in[10];
    const float* Wo = (const float*)d_in[11];
    const float* bo = (const float*)d_in[12];
    float* out = (float*)d_out;

    cudaFuncSetAttribute(gemm_qkv_kernel,
                         cudaFuncAttributeMaxDynamicSharedMemorySize, SMEM_GEMM);
    cudaFuncSetAttribute(gemm_out_kernel,
                         cudaFuncAttributeMaxDynamicSharedMemorySize, SMEM_GEMM);
    cudaFuncSetAttribute(flash_kernel,
                         cudaFuncAttributeMaxDynamicSharedMemorySize, SMEM_FLASH);

    mask_prepare_kernel<<<1, 256>>>(mask);

    const int nX = M * D, nW = D * D;
    split_x_kernel<<<dim3(nX / 8 / 256, 1, 3), 256>>>(q, kk, v);
    split_w_kernel<<<dim3(nW / 8 / 256, 1, 4), 256>>>(Wq, Wk, Wv, Wo);

    gemm_qkv_kernel<<<dim3(D / BN, M / BM, 3), 128, SMEM_GEMM>>>(bq, bk, bv);
    flash_kernel<<<dim3(S / QT, Bb * H), 256, SMEM_FLASH>>>(prev);
    gemm_out_kernel<<<dim3(D / BN, M / BM), 128, SMEM_GEMM>>>(bo, out);
}

// round 11
// speedup vs baseline: 1.3784x; 1.2558x over previous
#include <cuda_runtime.h>
#include <cuda_bf16.h>
#include <cstdint>
#include <cstring>

// ---------------------------------------------------------------------------
// MultiHeadAttention B=2,S=2048,D=1024,H=16,DK=DV=64
// split-bf16 mma.sync (3-term, fp32 acc).
// R11: cp.async.bulk + mbarrier for ALL tile loads (4-5 instrs per chunk vs
// 2048 cp.async). Scratch stored pre-tiled in the exact smem image.
// ---------------------------------------------------------------------------

namespace {
constexpr int  Bb = 2, S = 2048, D = 1024, H = 16;
constexpr int  M  = Bb * S;                    // 4096
constexpr float SCALE = 0.125f;

// projection GEMM tiling: CTA 128x128, 256 threads, 2x4 warps of 64x32
constexpr int BM = 128, BN = 128, KCH = 32;
constexpr int NC = D / KCH;                    // 32 chunks
constexpr int ROWPAD = 40;                     // bf16 elems per tile row (80 B)
constexpr int TILE_E = 128 * ROWPAD;           // 5120 elems per GEMM tile
constexpr int TILE_B = TILE_E * 2;             // 10240 B
constexpr int BUF_B  = 4 * TILE_B;             // 40960
constexpr int GEMM_MBAR = 2 * BUF_B;           // 81920
constexpr int SMEM_GEMM = GEMM_MBAR + 16;      // 81936

// flash tiling: q-tile 128, kv-tile 64, pitch 72 elems (144 B)
constexpr int QT = 128, KT = 64, RP = 72;
constexpr int NT = S / KT;                     // 32
constexpr int QTILE_E  = QT * RP;              // 9216 elems (18432 B)
constexpr int KVTILE_E = KT * RP;              // 4608 elems (9216 B)
constexpr int QBYTES   = QTILE_E * 2;          // 18432
constexpr int KVBYTES  = KVTILE_E * 2;         // 9216
constexpr int OFF_QH = 0, OFF_QL = QBYTES;
constexpr int OFF_KV = 2 * QBYTES;             // 36864
constexpr int KVBUF  = 4 * KVBYTES;            // 36864
constexpr int OFF_MK = OFF_KV + 2 * KVBUF;     // 110592
constexpr int FL_MBAR = OFF_MK + 128;          // 110720
constexpr int SMEM_FLASH = FL_MBAR + 16;       // 110736
}

// ---- device scratch (allocation-free), all pre-tiled layouts ----
// GEMM operand tiles: [rowblk][kchunk] of 128x40 elems
__device__ __nv_bfloat16 g_xh[3][(size_t)(M / 128) * NC * TILE_E];
__device__ __nv_bfloat16 g_xl[3][(size_t)(M / 128) * NC * TILE_E];
__device__ __nv_bfloat16 g_wh[4][(size_t)(D / 128) * NC * TILE_E];
__device__ __nv_bfloat16 g_wl[4][(size_t)(D / 128) * NC * TILE_E];
__device__ __nv_bfloat16 g_ah[(size_t)(M / 128) * NC * TILE_E];
__device__ __nv_bfloat16 g_al[(size_t)(M / 128) * NC * TILE_E];
// flash tiles per head: Q [bh][S/128] 128x72, K/V [bh][S/64] 64x72
__device__ __nv_bfloat16 g_qh[(size_t)Bb * H * (S / 128) * QTILE_E];
__device__ __nv_bfloat16 g_ql[(size_t)Bb * H * (S / 128) * QTILE_E];
__device__ __nv_bfloat16 g_kh[(size_t)Bb * H * (S / 64) * KVTILE_E];
__device__ __nv_bfloat16 g_kl[(size_t)Bb * H * (S / 64) * KVTILE_E];
__device__ __nv_bfloat16 g_vh[(size_t)Bb * H * (S / 64) * KVTILE_E];
__device__ __nv_bfloat16 g_vl[(size_t)Bb * H * (S / 64) * KVTILE_E];
__device__ unsigned char g_maskb[M];

// ---------------------------------------------------------------------------
// helpers
// ---------------------------------------------------------------------------
__device__ __forceinline__ uint32_t smem_u32(const void* p) {
    uint32_t a;
    asm("{ .reg .u64 t; cvta.to.shared.u64 t, %1; cvt.u32.u64 %0, t; }"
        : "=r"(a) : "l"(p));
    return a;
}
__device__ __forceinline__ void ldsm4(uint32_t* r, uint32_t a) {
    asm volatile("ldmatrix.sync.aligned.m8n8.x4.shared.b16 {%0,%1,%2,%3}, [%4];"
                 : "=r"(r[0]), "=r"(r[1]), "=r"(r[2]), "=r"(r[3]) : "r"(a));
}
__device__ __forceinline__ void ldsm4t(uint32_t* r, uint32_t a) {
    asm volatile("ldmatrix.sync.aligned.m8n8.x4.trans.shared.b16 {%0,%1,%2,%3}, [%4];"
                 : "=r"(r[0]), "=r"(r[1]), "=r"(r[2]), "=r"(r[3]) : "r"(a));
}
__device__ __forceinline__ uint32_t b2u(__nv_bfloat162 h) {
    uint32_t u;
    memcpy(&u, &h, 4);
    return u;
}
#define MMA16816(Dv, A0, A1, A2, A3, B0, B1)                                   \
    asm volatile(                                                              \
        "mma.sync.aligned.m16n8k16.row.col.f32.bf16.bf16.f32 "                 \
        "{%0,%1,%2,%3}, {%4,%5,%6,%7}, {%8,%9}, {%0,%1,%2,%3};"                \
        : "+f"((Dv)[0]), "+f"((Dv)[1]), "+f"((Dv)[2]), "+f"((Dv)[3])           \
        : "r"(A0), "r"(A1), "r"(A2), "r"(A3), "r"(B0), "r"(B1))

#define MBAR_INIT(mbar, cnt) \
    asm volatile("mbarrier.init.shared.b64 [%0], %1;" \
                 :: "r"((uint32_t)(mbar)), "r"((uint32_t)(cnt)) : "memory")
#define MBAR_EXPECT(mbar, bytes) \
    asm volatile("mbarrier.arrive.expect_tx.shared.b64 _, [%0], %1;" \
                 :: "r"((uint32_t)(mbar)), "r"((uint32_t)(bytes)) : "memory")
#define CPBULK(dst, src, bytes, mbar)                                          \
    asm volatile(                                                              \
        "cp.async.bulk.shared::cta.global.mbarrier::complete_tx::bytes "       \
        "[%0], [%1], %2, [%3];"                                                \
        :: "r"((uint32_t)(dst)), "l"(src), "r"((uint32_t)(bytes)),             \
           "r"((uint32_t)(mbar)) : "memory")

__device__ __forceinline__ void mbar_wait(uint32_t mbar, uint32_t parity) {
    asm volatile(
        "{\n\t.reg .pred P;\n"
        "W%=:\n\t"
        "mbarrier.try_wait.parity.acquire.cta.shared::cta.b64 P, [%0], %1;\n\t"
        "@P bra D%=;\n\t"
        "bra W%=;\n"
        "D%=:\n\t}"
        :: "r"(mbar), "r"(parity) : "memory");
}

// ---------------------------------------------------------------------------
// Mask normalization (sniff bool/int32/float32 storage)
// ---------------------------------------------------------------------------
__global__ void mask_prepare_kernel(const unsigned char* __restrict__ raw)
{
    __shared__ int flags;
    if (threadIdx.x == 0) flags = 0;
    __syncthreads();
    int f = 0;
    for (int i = threadIdx.x; i < M; i += blockDim.x) {
        unsigned char c = raw[i];
        if ((i & 3) != 0 && c != 0) f |= 1;
        if ((i & 3) == 3 && c == 0x3F) f |= 2;
    }
    if (f) atomicOr(&flags, f);
    __syncthreads();
    const int fl = flags;
    for (int i = threadIdx.x; i < M; i += blockDim.x) {
        unsigned char v;
        if (fl & 2)      v = (((const float*)raw)[i] != 0.0f);
        else if (fl & 1) v = (raw[i] != 0);
        else             v = (((const int*)raw)[i] != 0);
        g_maskb[i] = v;
    }
}

// ---------------------------------------------------------------------------
// Fused fp32 -> bf16 hi/lo splits into GEMM-tiled layout.
// ---------------------------------------------------------------------------
__device__ __forceinline__ void split8_to(const float* __restrict__ src, int i,
                                          __nv_bfloat16* __restrict__ hi,
                                          __nv_bfloat16* __restrict__ lo,
                                          size_t off)
{
    __nv_bfloat16 hs[8], ls[8];
#pragma unroll
    for (int half = 0; half < 2; ++half) {
        float4 v = *(const float4*)(src + i + half * 4);
        float xs[4] = {v.x, v.y, v.z, v.w};
#pragma unroll
        for (int j = 0; j < 4; ++j) {
            hs[half * 4 + j] = __float2bfloat16(xs[j]);
            ls[half * 4 + j] = __float2bfloat16(xs[j] - __bfloat162float(hs[half * 4 + j]));
        }
    }
    *(uint4*)(hi + off) = *(const uint4*)hs;
    *(uint4*)(lo + off) = *(const uint4*)ls;
}

__global__ void __launch_bounds__(256) split_x_kernel(
    const float* __restrict__ q, const float* __restrict__ k,
    const float* __restrict__ v)
{
    const int z = blockIdx.z;
    const float* src = (z == 0) ? q : (z == 1 ? k : v);
    int i = (blockIdx.x * blockDim.x + threadIdx.x) * 8;
    int m = i >> 10, kk = i & 1023;
    size_t off = ((size_t)(m >> 7) * NC + (kk >> 5)) * TILE_E
               + (m & 127) * ROWPAD + (kk & 31);
    split8_to(src, i, g_xh[z], g_xl[z], off);
}

__global__ void __launch_bounds__(256) split_w_kernel(
    const float* __restrict__ Wq, const float* __restrict__ Wk,
    const float* __restrict__ Wv, const float* __restrict__ Wo)
{
    const int z = blockIdx.z;
    const float* src = (z == 0) ? Wq : (z == 1 ? Wk : (z == 2 ? Wv : Wo));
    int i = (blockIdx.x * blockDim.x + threadIdx.x) * 8;
    int n = i >> 10, kk = i & 1023;
    size_t off = ((size_t)(n >> 7) * NC + (kk >> 5)) * TILE_E
               + (n & 127) * ROWPAD + (kk & 31);
    split8_to(src, i, g_wh[z], g_wl[z], off);
}

// ---------------------------------------------------------------------------
// split-bf16 GEMM with bulk-copied tiles.
//   mode 0: fp32 dst[m][D]
//   mode 1: Q-tiled bf16 hi/lo (value*(scale)), tiles 128x72
//   mode 2: K/V-tiled bf16 hi/lo, tiles 64x72
// ---------------------------------------------------------------------------
__device__ __forceinline__ void gemm_core(
    const __nv_bfloat16* __restrict__ Ah,
    const __nv_bfloat16* __restrict__ Al,
    const __nv_bfloat16* __restrict__ Bh,
    const __nv_bfloat16* __restrict__ Bl,
    const float* __restrict__ bias,
    float* __restrict__ dst,
    __nv_bfloat16* __restrict__ dsth,
    __nv_bfloat16* __restrict__ dstl,
    float scale, int mode)
{
    extern __shared__ char smraw[];
    const uint32_t sb  = smem_u32(smraw);
    const uint32_t mb0 = sb + GEMM_MBAR;

    const int tid  = threadIdx.x;
    const int lane = tid & 31;
    const int wid  = tid >> 5;
    const int mw   = wid & 1;
    const int nw   = wid >> 1;
    const int m0   = blockIdx.y * BM;
    const int n0   = blockIdx.x * BN;

    // global tile bases (elems)
    const size_t aBase = (size_t)(m0 >> 7) * NC * TILE_E;
    const size_t bBase = (size_t)(n0 >> 7) * NC * TILE_E;

    auto tile = [&](int buf, int t) -> uint32_t { return sb + buf * BUF_B + t * TILE_B; };

    const int q8   = lane >> 3;
    const int l8   = lane & 7;
    const int a_row = (q8 & 1) * 8 + l8;
    const int a_ke  = (q8 >> 1) * 8;
    const int b_row = (q8 >> 1) * 8 + l8;
    const int b_ke  = (q8 & 1) * 8;

    float d[4][4][4];
#pragma unroll
    for (int i = 0; i < 4; ++i)
#pragma unroll
        for (int j = 0; j < 4; ++j)
#pragma unroll
            for (int r = 0; r < 4; ++r) d[i][j][r] = 0.f;

    if (tid == 0) {
        MBAR_INIT(mb0, 1);
        MBAR_INIT(mb0 + 8, 1);
    }
    __syncthreads();
    if (tid == 0) {
#pragma unroll
        for (int p = 0; p < 2; ++p) {
            MBAR_EXPECT(mb0 + p * 8, 4 * TILE_B);
            CPBULK(tile(p, 0), Ah + aBase + (size_t)p * TILE_E, TILE_B, mb0 + p * 8);
            CPBULK(tile(p, 1), Al + aBase + (size_t)p * TILE_E, TILE_B, mb0 + p * 8);
            CPBULK(tile(p, 2), Bh + bBase + (size_t)p * TILE_E, TILE_B, mb0 + p * 8);
            CPBULK(tile(p, 3), Bl + bBase + (size_t)p * TILE_E, TILE_B, mb0 + p * 8);
        }
    }

    const int rq = lane >> 2;
    const int cq = (lane & 3) * 2;

    for (int c = 0; c < NC; ++c) {
        const int buf = c & 1;
        mbar_wait(mb0 + buf * 8, (uint32_t)((c >> 1) & 1));

        const uint32_t xh = tile(buf, 0), xl = tile(buf, 1);
        const uint32_t wh = tile(buf, 2), wl = tile(buf, 3);

#pragma unroll
        for (int kk2 = 0; kk2 < 2; ++kk2) {
            const int kk = kk2 * 16;
            uint32_t bhf[8], blf[8];
#pragma unroll
            for (int jp = 0; jp < 2; ++jp) {
                int rn = nw * 32 + jp * 16 + b_row;
                uint32_t off = (uint32_t)((rn * ROWPAD + kk + b_ke) * 2);
                ldsm4(&bhf[jp * 4], wh + off);
                ldsm4(&blf[jp * 4], wl + off);
            }
#pragma unroll
            for (int mi = 0; mi < 4; ++mi) {
                int rm = mw * 64 + mi * 16 + a_row;
                uint32_t off = (uint32_t)((rm * ROWPAD + kk + a_ke) * 2);
                uint32_t a[4], al4[4];
                ldsm4(a, xh + off);
                ldsm4(al4, xl + off);
#pragma unroll
                for (int j = 0; j < 4; ++j) {
                    MMA16816(d[mi][j], a[0], a[1], a[2], a[3], bhf[j * 2], bhf[j * 2 + 1]);
                    MMA16816(d[mi][j], a[0], a[1], a[2], a[3], blf[j * 2], blf[j * 2 + 1]);
                    MMA16816(d[mi][j], al4[0], al4[1], al4[2], al4[3], bhf[j * 2], bhf[j * 2 + 1]);
                }
            }
        }
        __syncthreads();
        if (c + 2 < NC && tid == 0) {
            MBAR_EXPECT(mb0 + buf * 8, 4 * TILE_B);
            CPBULK(tile(buf, 0), Ah + aBase + (size_t)(c + 2) * TILE_E, TILE_B, mb0 + buf * 8);
            CPBULK(tile(buf, 1), Al + aBase + (size_t)(c + 2) * TILE_E, TILE_B, mb0 + buf * 8);
            CPBULK(tile(buf, 2), Bh + bBase + (size_t)(c + 2) * TILE_E, TILE_B, mb0 + buf * 8);
            CPBULK(tile(buf, 3), Bl + bBase + (size_t)(c + 2) * TILE_E, TILE_B, mb0 + buf * 8);
        }
    }

#pragma unroll
    for (int mi = 0; mi < 4; ++mi) {
#pragma unroll
        for (int j = 0; j < 4; ++j) {
            int r0 = m0 + mw * 64 + mi * 16 + rq;
            int n  = n0 + nw * 32 + j * 8 + cq;
            float b0 = bias[n], b1 = bias[n + 1];
#pragma unroll
            for (int h2 = 0; h2 < 2; ++h2) {
                int r = r0 + h2 * 8;
                float v0 = d[mi][j][h2 * 2 + 0] + b0;
                float v1 = d[mi][j][h2 * 2 + 1] + b1;
                if (mode == 0) {
                    float2 o; o.x = v0; o.y = v1;
                    *(float2*)(dst + (size_t)r * D + n) = o;
                } else {
                    v0 *= scale; v1 *= scale;
                    int b = r >> 11, srow = r & 2047;
                    int hh = n >> 6, dd = n & 63;
                    int bh = b * H + hh;
                    size_t base;
                    if (mode == 1)
                        base = ((size_t)bh * (S / 128) + (srow >> 7)) * QTILE_E
                             + (srow & 127) * RP + dd;
                    else
                        base = ((size_t)bh * (S / 64) + (srow >> 6)) * KVTILE_E
                             + (srow & 63) * RP + dd;
                    __nv_bfloat16 h0 = __float2bfloat16(v0);
                    __nv_bfloat16 h1 = __float2bfloat16(v1);
                    __nv_bfloat162 hp; hp.x = h0; hp.y = h1;
                    __nv_bfloat162 lp;
                    lp.x = __float2bfloat16(v0 - __bfloat162float(h0));
                    lp.y = __float2bfloat16(v1 - __bfloat162float(h1));
                    *(uint32_t*)(dsth + base) = b2u(hp);
                    *(uint32_t*)(dstl + base) = b2u(lp);
                }
            }
        }
    }
}

__global__ void __launch_bounds__(256, 2) gemm_qkv_kernel(
    const float* __restrict__ bq, const float* __restrict__ bk,
    const float* __restrict__ bv)
{
    const int z = blockIdx.z;
    const float* bias = (z == 0) ? bq : (z == 1 ? bk : bv);
    __nv_bfloat16* dh = (z == 0) ? g_qh : (z == 1 ? g_kh : g_vh);
    __nv_bfloat16* dl = (z == 0) ? g_ql : (z == 1 ? g_kl : g_vl);
    float scale = (z == 0) ? SCALE : 1.0f;
    gemm_core(g_xh[z], g_xl[z], g_wh[z], g_wl[z], bias,
              nullptr, dh, dl, scale, (z == 0) ? 1 : 2);
}

__global__ void __launch_bounds__(256, 2) gemm_out_kernel(
    const float* __restrict__ bo, float* __restrict__ out)
{
    gemm_core(g_ah, g_al, g_wh[3], g_wl[3], bo, out, nullptr, nullptr, 1.0f, 0);
}

// ---------------------------------------------------------------------------
// Flash attention, split-bf16, QT=128, KT=64, 8 warps, 2 CTAs/SM.
// All tile loads via cp.async.bulk + mbarrier (mask rides as 5th bulk).
// ---------------------------------------------------------------------------
__global__ void __launch_bounds__(256, 2) flash_kernel(const float* __restrict__ prev)
{
    extern __shared__ char sm[];
    const uint32_t sb  = smem_u32(sm);
    const uint32_t mb0 = sb + FL_MBAR;

    const int tid  = threadIdx.x;
    const int lane = tid & 31;
    const int w    = tid >> 5;
    const int bh   = blockIdx.y;
    const int b    = bh >> 4;
    const int hq   = bh & 15;
    const int q0   = blockIdx.x * QT;
    const int rq   = lane >> 2;
    const int cq   = (lane & 3) * 2;
    const int mrow = w * 16;

    const __nv_bfloat16* Qht = g_qh + ((size_t)bh * (S / 128) + blockIdx.x) * QTILE_E;
    const __nv_bfloat16* Qlt = g_ql + ((size_t)bh * (S / 128) + blockIdx.x) * QTILE_E;
    const __nv_bfloat16* Kht = g_kh + (size_t)bh * (S / 64) * KVTILE_E;
    const __nv_bfloat16* Klt = g_kl + (size_t)bh * (S / 64) * KVTILE_E;
    const __nv_bfloat16* Vht = g_vh + (size_t)bh * (S / 64) * KVTILE_E;
    const __nv_bfloat16* Vlt = g_vl + (size_t)bh * (S / 64) * KVTILE_E;
    const unsigned char* mkg = g_maskb + b * S;

    if (tid == 0) {
        MBAR_INIT(mb0, 1);
        MBAR_INIT(mb0 + 8, 1);
    }
    __syncthreads();
    if (tid == 0) {
        // phase 0 of mbar0: Q (both arrays) + KV tile 0 + mask0
        MBAR_EXPECT(mb0, 2 * QBYTES + 4 * KVBYTES + 64);
        CPBULK(sb + OFF_QH, Qht, QBYTES, mb0);
        CPBULK(sb + OFF_QL, Qlt, QBYTES, mb0);
        CPBULK(sb + OFF_KV + 0 * KVBUF + 0 * KVBYTES, Kht, KVBYTES, mb0);
        CPBULK(sb + OFF_KV + 0 * KVBUF + 1 * KVBYTES, Klt, KVBYTES, mb0);
        CPBULK(sb + OFF_KV + 0 * KVBUF + 2 * KVBYTES, Vht, KVBYTES, mb0);
        CPBULK(sb + OFF_KV + 0 * KVBUF + 3 * KVBYTES, Vlt, KVBYTES, mb0);
        CPBULK(sb + OFF_MK, mkg, 64, mb0);
        // phase 0 of mbar1: KV tile 1 + mask1
        MBAR_EXPECT(mb0 + 8, 4 * KVBYTES + 64);
        CPBULK(sb + OFF_KV + 1 * KVBUF + 0 * KVBYTES, Kht + KVTILE_E, KVBYTES, mb0 + 8);
        CPBULK(sb + OFF_KV + 1 * KVBUF + 1 * KVBYTES, Klt + KVTILE_E, KVBYTES, mb0 + 8);
        CPBULK(sb + OFF_KV + 1 * KVBUF + 2 * KVBYTES, Vht + KVTILE_E, KVBYTES, mb0 + 8);
        CPBULK(sb + OFF_KV + 1 * KVBUF + 3 * KVBYTES, Vlt + KVTILE_E, KVBYTES, mb0 + 8);
        CPBULK(sb + OFF_MK + 64, mkg + 64, 64, mb0 + 8);
    }

    float m_i[2] = {-3.0e38f, -3.0e38f};
    float l_i[2] = {0.f, 0.f};
    float o[8][4];
#pragma unroll
    for (int j = 0; j < 8; ++j)
#pragma unroll
        for (int r = 0; r < 4; ++r) o[j][r] = 0.f;

    const float* prow0 = prev + ((size_t)bh * S + q0 + mrow + rq) * S;
    const float* prow1 = prow0 + (size_t)8 * S;

    for (int t = 0; t < NT; ++t) {
        const int buf = t & 1;
        mbar_wait(mb0 + buf * 8, (uint32_t)((t >> 1) & 1));

        const uint32_t KH = sb + OFF_KV + buf * KVBUF;
        const uint32_t KL = KH + KVBYTES;
        const uint32_t VH = KL + KVBYTES;
        const uint32_t VL = VH + KVBYTES;
        const uint32_t QH = sb + OFF_QH, QL = sb + OFF_QL;

        // --- QK^T (3 terms) ---
        float s[8][4];
#pragma unroll
        for (int j = 0; j < 8; ++j)
#pragma unroll
            for (int r = 0; r < 4; ++r) s[j][r] = 0.f;

#pragma unroll
        for (int kc = 0; kc < 4; ++kc) {
            uint32_t aoff = (uint32_t)((mrow + (lane & 15)) * (RP * 2)
                                       + kc * 32 + (lane >> 4) * 16);
            uint32_t ah[4], al[4];
            ldsm4(ah, QH + aoff);
            ldsm4(al, QL + aoff);
#pragma unroll
            for (int jp = 0; jp < 4; ++jp) {
                uint32_t boff = (uint32_t)(((jp * 2 + (lane >> 4)) * 8 + (lane & 7)) * (RP * 2)
                                           + kc * 32 + ((lane >> 3) & 1) * 16);
                uint32_t bh4[4], bl4[4];
                ldsm4(bh4, KH + boff);
                ldsm4(bl4, KL + boff);
                MMA16816(s[2 * jp],     ah[0], ah[1], ah[2], ah[3], bh4[0], bh4[1]);
                MMA16816(s[2 * jp],     al[0], al[1], al[2], al[3], bh4[0], bh4[1]);
                MMA16816(s[2 * jp],     ah[0], ah[1], ah[2], ah[3], bl4[0], bl4[1]);
                MMA16816(s[2 * jp + 1], ah[0], ah[1], ah[2], ah[3], bh4[2], bh4[3]);
                MMA16816(s[2 * jp + 1], al[0], al[1], al[2], al[3], bh4[2], bh4[3]);
                MMA16816(s[2 * jp + 1], ah[0], ah[1], ah[2], ah[3], bl4[2], bl4[3]);
            }
        }

        // --- + prev, mask ---
#pragma unroll
        for (int j = 0; j < 8; ++j) {
            const unsigned char* mkp = (const unsigned char*)(sm + OFF_MK + buf * 64 + j * 8 + cq);
            unsigned char mk0 = mkp[0], mk1 = mkp[1];
            float2 p0 = *(const float2*)(prow0 + (size_t)t * KT + j * 8 + cq);
            float2 p1 = *(const float2*)(prow1 + (size_t)t * KT + j * 8 + cq);
            s[j][0] = mk0 ? -1.0e30f : s[j][0] + p0.x;
            s[j][1] = mk1 ? -1.0e30f : s[j][1] + p0.y;
            s[j][2] = mk0 ? -1.0e30f : s[j][2] + p1.x;
            s[j][3] = mk1 ? -1.0e30f : s[j][3] + p1.y;
        }

        // --- online softmax (rows rq, rq+8) ---
#pragma unroll
        for (int r = 0; r < 2; ++r) {
            float mx = -3.0e38f;
#pragma unroll
            for (int j = 0; j < 8; ++j)
                mx = fmaxf(mx, fmaxf(s[j][2 * r], s[j][2 * r + 1]));
            mx = fmaxf(mx, __shfl_xor_sync(0xffffffffu, mx, 1));
            mx = fmaxf(mx, __shfl_xor_sync(0xffffffffu, mx, 2));
            float m_new = fmaxf(m_i[r], mx);
            float corr  = __expf(m_i[r] - m_new);
            float rs = 0.f;
#pragma unroll
            for (int j = 0; j < 8; ++j) {
                s[j][2 * r]     = __expf(s[j][2 * r]     - m_new);
                s[j][2 * r + 1] = __expf(s[j][2 * r + 1] - m_new);
                rs += s[j][2 * r] + s[j][2 * r + 1];
            }
            rs += __shfl_xor_sync(0xffffffffu, rs, 1);
            rs += __shfl_xor_sync(0xffffffffu, rs, 2);
            l_i[r] = l_i[r] * corr + rs;
            m_i[r] = m_new;
#pragma unroll
            for (int j = 0; j < 8; ++j) {
                o[j][2 * r]     *= corr;
                o[j][2 * r + 1] *= corr;
            }
        }

        // --- P@V (3 terms), P from registers ---
#pragma unroll
        for (int kc2 = 0; kc2 < 4; ++kc2) {
            const int j0 = 2 * kc2, j1 = j0 + 1;
            uint32_t pah[4], pal[4];
#pragma unroll
            for (int q = 0; q < 4; ++q) {
                const int jt = (q & 2) ? j1 : j0;
                const int rr = (q & 1) ? 2 : 0;
                float x = s[jt][rr], y = s[jt][rr + 1];
                __nv_bfloat16 hx = __float2bfloat16(x);
                __nv_bfloat16 hy = __float2bfloat16(y);
                __nv_bfloat162 hp; hp.x = hx; hp.y = hy;
                __nv_bfloat162 lp;
                lp.x = __float2bfloat16(x - __bfloat162float(hx));
                lp.y = __float2bfloat16(y - __bfloat162float(hy));
                pah[q] = b2u(hp);
                pal[q] = b2u(lp);
            }
#pragma unroll
            for (int jp = 0; jp < 4; ++jp) {
                uint32_t voff = (uint32_t)((kc2 * 16 + ((lane >> 3) & 1) * 8 + (lane & 7)) * (RP * 2)
                                           + (jp * 2 + (lane >> 4)) * 16);
                uint32_t vh4[4], vl4[4];
                ldsm4t(vh4, VH + voff);
                ldsm4t(vl4, VL + voff);
                MMA16816(o[2 * jp],     pah[0], pah[1], pah[2], pah[3], vh4[0], vh4[1]);
                MMA16816(o[2 * jp],     pal[0], pal[1], pal[2], pal[3], vh4[0], vh4[1]);
                MMA16816(o[2 * jp],     pah[0], pah[1], pah[2], pah[3], vl4[0], vl4[1]);
                MMA16816(o[2 * jp + 1], pah[0], pah[1], pah[2], pah[3], vh4[2], vh4[3]);
                MMA16816(o[2 * jp + 1], pal[0], pal[1], pal[2], pal[3], vh4[2], vh4[3]);
                MMA16816(o[2 * jp + 1], pah[0], pah[1], pah[2], pah[3], vl4[2], vl4[3]);
            }
        }

        __syncthreads();
        if (t + 2 < NT && tid == 0) {
            MBAR_EXPECT(mb0 + buf * 8, 4 * KVBYTES + 64);
            CPBULK(sb + OFF_KV + buf * KVBUF + 0 * KVBYTES, Kht + (size_t)(t + 2) * KVTILE_E, KVBYTES, mb0 + buf * 8);
            CPBULK(sb + OFF_KV + buf * KVBUF + 1 * KVBYTES, Klt + (size_t)(t + 2) * KVTILE_E, KVBYTES, mb0 + buf * 8);
            CPBULK(sb + OFF_KV + buf * KVBUF + 2 * KVBYTES, Vht + (size_t)(t + 2) * KVTILE_E, KVBYTES, mb0 + buf * 8);
            CPBULK(sb + OFF_KV + buf * KVBUF + 3 * KVBYTES, Vlt + (size_t)(t + 2) * KVTILE_E, KVBYTES, mb0 + buf * 8);
            CPBULK(sb + OFF_MK + buf * 64, mkg + (size_t)(t + 2) * 64, 64, mb0 + buf * 8);
        }
    }

    // --- epilogue: normalize, emit bf16 hi/lo attn into GEMM-tiled layout ---
    const float inv0 = 1.0f / fmaxf(l_i[0], 1e-30f);
    const float inv1 = 1.0f / fmaxf(l_i[1], 1e-30f);
    const size_t mrow0 = (size_t)b * S + q0 + mrow + rq;
#pragma unroll
    for (int jn = 0; jn < 8; ++jn) {
        const int col = hq * 64 + jn * 8 + cq;
        float v0 = o[jn][0] * inv0, v1 = o[jn][1] * inv0;
        float v2 = o[jn][2] * inv1, v3 = o[jn][3] * inv1;

#pragma unroll
        for (int h2 = 0; h2 < 2; ++h2) {
            size_t m = mrow0 + h2 * 8;
            float x = h2 ? v2 : v0, y = h2 ? v3 : v1;
            size_t off = ((m >> 7) * (size_t)NC + (col >> 5)) * TILE_E
                       + (m & 127) * ROWPAD + (col & 31);
            __nv_bfloat16 hx = __float2bfloat16(x), hy = __float2bfloat16(y);
            __nv_bfloat162 hp; hp.x = hx; hp.y = hy;
            __nv_bfloat162 lp;
            lp.x = __float2bfloat16(x - __bfloat162float(hx));
            lp.y = __float2bfloat16(y - __bfloat162float(hy));
            *(uint32_t*)(g_ah + off) = b2u(hp);
            *(uint32_t*)(g_al + off) = b2u(lp);
        }
    }
}

// ---------------------------------------------------------------------------
// Inputs: 0:q 1:k 2:v 3:prev 4:mask 5:Wq 6:bq 7:Wk 8:bk 9:Wv 10:bv 11:Wo 12:bo
// ---------------------------------------------------------------------------
extern "C" void kernel_launch(void* const* d_in, const int* in_sizes, int n_in,
                              void* d_out, int out_size)
{
    (void)in_sizes; (void)n_in; (void)out_size;

    const float* q    = (const float*)d_in[0];
    const float* kk   = (const float*)d_in[1];
    const float* v    = (const float*)d_in[2];
    const float* prev = (const float*)d_in[3];
    const unsigned char* mask = (const unsigned char*)d_in[4];
    const float* Wq = (const float*)d_in[5];
    const float* bq = (const float*)d_in[6];
    const float* Wk = (const float*)d_in[7];
    const float* bk = (const float*)d_in[8];
    const float* Wv = (const float*)d_in[9];
    const float* bv = (const float*)d_in[10];
    const float* Wo = (const float*)d_in[11];
    const float* bo = (const float*)d_in[12];
    float* out = (float*)d_out;

    cudaFuncSetAttribute(gemm_qkv_kernel,
                         cudaFuncAttributeMaxDynamicSharedMemorySize, SMEM_GEMM);
    cudaFuncSetAttribute(gemm_out_kernel,
                         cudaFuncAttributeMaxDynamicSharedMemorySize, SMEM_GEMM);
    cudaFuncSetAttribute(flash_kernel,
                         cudaFuncAttributeMaxDynamicSharedMemorySize, SMEM_FLASH);

    mask_prepare_kernel<<<1, 256>>>(mask);

    const int nX = M * D, nW = D * D;
    split_x_kernel<<<dim3(nX / 8 / 256, 1, 3), 256>>>(q, kk, v);
    split_w_kernel<<<dim3(nW / 8 / 256, 1, 4), 256>>>(Wq, Wk, Wv, Wo);

    gemm_qkv_kernel<<<dim3(D / BN, M / BM, 3), 256, SMEM_GEMM>>>(bq, bk, bv);
    flash_kernel<<<dim3(S / QT, Bb * H), 256, SMEM_FLASH>>>(prev);
    gemm_out_kernel<<<dim3(D / BN, M / BM), 256, SMEM_GEMM>>>(bo, out);
}

// round 12
// speedup vs baseline: 2.4876x; 1.8047x over previous
#include <cuda_runtime.h>
#include <cuda_fp16.h>
#include <cstdint>
#include <cstring>

// ---------------------------------------------------------------------------
// MultiHeadAttention B=2,S=2048,D=1024,H=16,DK=DV=64
// R12: single-term f16 mma.sync everywhere (11-bit mantissa => ~3e-4 rel err,
// under the 1e-3 gate). 3x fewer MMAs than split-bf16; halved crossbar/bulk
// bytes; GEMM gets a 4-deep cp.async.bulk pipeline.
// ---------------------------------------------------------------------------

namespace {
constexpr int  Bb = 2, S = 2048, D = 1024, H = 16;
constexpr int  M  = Bb * S;                    // 4096
constexpr float SCALE = 0.125f;

// projection GEMM tiling: CTA 128x128, 256 threads, 2x4 warps of 64x32
constexpr int BM = 128, BN = 128, KCH = 32;
constexpr int NC = D / KCH;                    // 32 chunks
constexpr int ROWPAD = 40;                     // f16 elems per tile row (80 B)
constexpr int TILE_E = 128 * ROWPAD;           // 5120 elems per GEMM tile
constexpr int TILE_B = TILE_E * 2;             // 10240 B
constexpr int NBUF   = 4;                      // 4-deep pipeline
constexpr int BUF_B  = 2 * TILE_B;             // X + W per buffer = 20480
constexpr int GEMM_MBAR = NBUF * BUF_B;        // 81920
constexpr int SMEM_GEMM = GEMM_MBAR + NBUF * 8;

// flash tiling: q-tile 128, kv-tile 64, pitch 72 elems (144 B)
constexpr int QT = 128, KT = 64, RP = 72;
constexpr int NT = S / KT;                     // 32
constexpr int QTILE_E  = QT * RP;              // 9216 elems
constexpr int KVTILE_E = KT * RP;              // 4608 elems
constexpr int QBYTES   = QTILE_E * 2;          // 18432
constexpr int KVBYTES  = KVTILE_E * 2;         // 9216
constexpr int OFF_Q  = 0;
constexpr int OFF_KV = QBYTES;                 // 18432
constexpr int KVBUF  = 2 * KVBYTES;            // K + V = 18432
constexpr int OFF_MK = OFF_KV + 2 * KVBUF;     // 55296
constexpr int FL_MBAR = OFF_MK + 128;          // 55424
constexpr int SMEM_FLASH = FL_MBAR + 16;       // 55440
}

// ---- device scratch (allocation-free), all pre-tiled layouts, f16 ----
__device__ __half g_x[3][(size_t)(M / 128) * NC * TILE_E];
__device__ __half g_w[4][(size_t)(D / 128) * NC * TILE_E];
__device__ __half g_a[(size_t)(M / 128) * NC * TILE_E];
__device__ __half g_q[(size_t)Bb * H * (S / 128) * QTILE_E];
__device__ __half g_k[(size_t)Bb * H * (S / 64) * KVTILE_E];
__device__ __half g_v[(size_t)Bb * H * (S / 64) * KVTILE_E];
__device__ unsigned char g_maskb[M];

// ---------------------------------------------------------------------------
// helpers
// ---------------------------------------------------------------------------
__device__ __forceinline__ uint32_t smem_u32(const void* p) {
    uint32_t a;
    asm("{ .reg .u64 t; cvta.to.shared.u64 t, %1; cvt.u32.u64 %0, t; }"
        : "=r"(a) : "l"(p));
    return a;
}
__device__ __forceinline__ void ldsm4(uint32_t* r, uint32_t a) {
    asm volatile("ldmatrix.sync.aligned.m8n8.x4.shared.b16 {%0,%1,%2,%3}, [%4];"
                 : "=r"(r[0]), "=r"(r[1]), "=r"(r[2]), "=r"(r[3]) : "r"(a));
}
__device__ __forceinline__ void ldsm4t(uint32_t* r, uint32_t a) {
    asm volatile("ldmatrix.sync.aligned.m8n8.x4.trans.shared.b16 {%0,%1,%2,%3}, [%4];"
                 : "=r"(r[0]), "=r"(r[1]), "=r"(r[2]), "=r"(r[3]) : "r"(a));
}
__device__ __forceinline__ uint32_t h2u(__half2 h) {
    uint32_t u;
    memcpy(&u, &h, 4);
    return u;
}
#define MMAF16(Dv, A0, A1, A2, A3, B0, B1)                                     \
    asm volatile(                                                              \
        "mma.sync.aligned.m16n8k16.row.col.f32.f16.f16.f32 "                   \
        "{%0,%1,%2,%3}, {%4,%5,%6,%7}, {%8,%9}, {%0,%1,%2,%3};"                \
        : "+f"((Dv)[0]), "+f"((Dv)[1]), "+f"((Dv)[2]), "+f"((Dv)[3])           \
        : "r"(A0), "r"(A1), "r"(A2), "r"(A3), "r"(B0), "r"(B1))

#define MBAR_INIT(mbar, cnt) \
    asm volatile("mbarrier.init.shared.b64 [%0], %1;" \
                 :: "r"((uint32_t)(mbar)), "r"((uint32_t)(cnt)) : "memory")
#define MBAR_EXPECT(mbar, bytes) \
    asm volatile("mbarrier.arrive.expect_tx.shared.b64 _, [%0], %1;" \
                 :: "r"((uint32_t)(mbar)), "r"((uint32_t)(bytes)) : "memory")
#define CPBULK(dst, src, bytes, mbar)                                          \
    asm volatile(                                                              \
        "cp.async.bulk.shared::cta.global.mbarrier::complete_tx::bytes "       \
        "[%0], [%1], %2, [%3];"                                                \
        :: "r"((uint32_t)(dst)), "l"(src), "r"((uint32_t)(bytes)),             \
           "r"((uint32_t)(mbar)) : "memory")

__device__ __forceinline__ void mbar_wait(uint32_t mbar, uint32_t parity) {
    asm volatile(
        "{\n\t.reg .pred P;\n"
        "W%=:\n\t"
        "mbarrier.try_wait.parity.acquire.cta.shared::cta.b64 P, [%0], %1;\n\t"
        "@P bra D%=;\n\t"
        "bra W%=;\n"
        "D%=:\n\t}"
        :: "r"(mbar), "r"(parity) : "memory");
}

// ---------------------------------------------------------------------------
// Mask normalization (sniff bool/int32/float32 storage)
// ---------------------------------------------------------------------------
__global__ void mask_prepare_kernel(const unsigned char* __restrict__ raw)
{
    __shared__ int flags;
    if (threadIdx.x == 0) flags = 0;
    __syncthreads();
    int f = 0;
    for (int i = threadIdx.x; i < M; i += blockDim.x) {
        unsigned char c = raw[i];
        if ((i & 3) != 0 && c != 0) f |= 1;
        if ((i & 3) == 3 && c == 0x3F) f |= 2;
    }
    if (f) atomicOr(&flags, f);
    __syncthreads();
    const int fl = flags;
    for (int i = threadIdx.x; i < M; i += blockDim.x) {
        unsigned char v;
        if (fl & 2)      v = (((const float*)raw)[i] != 0.0f);
        else if (fl & 1) v = (raw[i] != 0);
        else             v = (((const int*)raw)[i] != 0);
        g_maskb[i] = v;
    }
}

// ---------------------------------------------------------------------------
// fp32 -> f16 converts into GEMM-tiled layout (128x40 tiles).
// ---------------------------------------------------------------------------
__device__ __forceinline__ void conv8_to(const float* __restrict__ src, int i,
                                         __half* __restrict__ dst, size_t off)
{
    __half hs[8];
#pragma unroll
    for (int half_ = 0; half_ < 2; ++half_) {
        float4 v = *(const float4*)(src + i + half_ * 4);
        hs[half_ * 4 + 0] = __float2half_rn(v.x);
        hs[half_ * 4 + 1] = __float2half_rn(v.y);
        hs[half_ * 4 + 2] = __float2half_rn(v.z);
        hs[half_ * 4 + 3] = __float2half_rn(v.w);
    }
    *(uint4*)(dst + off) = *(const uint4*)hs;
}

__global__ void __launch_bounds__(256) conv_x_kernel(
    const float* __restrict__ q, const float* __restrict__ k,
    const float* __restrict__ v)
{
    const int z = blockIdx.z;
    const float* src = (z == 0) ? q : (z == 1 ? k : v);
    int i = (blockIdx.x * blockDim.x + threadIdx.x) * 8;
    int m = i >> 10, kk = i & 1023;
    size_t off = ((size_t)(m >> 7) * NC + (kk >> 5)) * TILE_E
               + (m & 127) * ROWPAD + (kk & 31);
    conv8_to(src, i, g_x[z], off);
}

__global__ void __launch_bounds__(256) conv_w_kernel(
    const float* __restrict__ Wq, const float* __restrict__ Wk,
    const float* __restrict__ Wv, const float* __restrict__ Wo)
{
    const int z = blockIdx.z;
    const float* src = (z == 0) ? Wq : (z == 1 ? Wk : (z == 2 ? Wv : Wo));
    int i = (blockIdx.x * blockDim.x + threadIdx.x) * 8;
    int n = i >> 10, kk = i & 1023;
    size_t off = ((size_t)(n >> 7) * NC + (kk >> 5)) * TILE_E
               + (n & 127) * ROWPAD + (kk & 31);
    conv8_to(src, i, g_w[z], off);
}

// ---------------------------------------------------------------------------
// f16 GEMM with 4-deep bulk pipeline. Epilogue modes:
//   mode 0: fp32 dst[m][D]
//   mode 1: Q-tiled f16 (value*scale), tiles 128x72
//   mode 2: K/V-tiled f16, tiles 64x72
// ---------------------------------------------------------------------------
__device__ __forceinline__ void gemm_core(
    const __half* __restrict__ A,
    const __half* __restrict__ B,
    const float* __restrict__ bias,
    float* __restrict__ dst,
    __half* __restrict__ dsth,
    float scale, int mode)
{
    extern __shared__ char smraw[];
    const uint32_t sb  = smem_u32(smraw);
    const uint32_t mb0 = sb + GEMM_MBAR;

    const int tid  = threadIdx.x;
    const int lane = tid & 31;
    const int wid  = tid >> 5;
    const int mw   = wid & 1;
    const int nw   = wid >> 1;
    const int m0   = blockIdx.y * BM;
    const int n0   = blockIdx.x * BN;

    const size_t aBase = (size_t)(m0 >> 7) * NC * TILE_E;
    const size_t bBase = (size_t)(n0 >> 7) * NC * TILE_E;

    auto tileX = [&](int buf) -> uint32_t { return sb + buf * BUF_B; };
    auto tileW = [&](int buf) -> uint32_t { return sb + buf * BUF_B + TILE_B; };

    const int q8   = lane >> 3;
    const int l8   = lane & 7;
    const int a_row = (q8 & 1) * 8 + l8;
    const int a_ke  = (q8 >> 1) * 8;
    const int b_row = (q8 >> 1) * 8 + l8;
    const int b_ke  = (q8 & 1) * 8;

    float d[4][4][4];
#pragma unroll
    for (int i = 0; i < 4; ++i)
#pragma unroll
        for (int j = 0; j < 4; ++j)
#pragma unroll
            for (int r = 0; r < 4; ++r) d[i][j][r] = 0.f;

    if (tid == 0) {
#pragma unroll
        for (int p = 0; p < NBUF; ++p) MBAR_INIT(mb0 + p * 8, 1);
    }
    __syncthreads();
    if (tid == 0) {
#pragma unroll
        for (int p = 0; p < NBUF; ++p) {
            MBAR_EXPECT(mb0 + p * 8, 2 * TILE_B);
            CPBULK(tileX(p), A + aBase + (size_t)p * TILE_E, TILE_B, mb0 + p * 8);
            CPBULK(tileW(p), B + bBase + (size_t)p * TILE_E, TILE_B, mb0 + p * 8);
        }
    }

    const int rq = lane >> 2;
    const int cq = (lane & 3) * 2;

    for (int c = 0; c < NC; ++c) {
        const int buf = c & (NBUF - 1);
        mbar_wait(mb0 + buf * 8, (uint32_t)((c >> 2) & 1));

        const uint32_t xs = tileX(buf), ws = tileW(buf);

#pragma unroll
        for (int kk2 = 0; kk2 < 2; ++kk2) {
            const int kk = kk2 * 16;
            uint32_t bf[8];
#pragma unroll
            for (int jp = 0; jp < 2; ++jp) {
                int rn = nw * 32 + jp * 16 + b_row;
                ldsm4(&bf[jp * 4], ws + (uint32_t)((rn * ROWPAD + kk + b_ke) * 2));
            }
#pragma unroll
            for (int mi = 0; mi < 4; ++mi) {
                int rm = mw * 64 + mi * 16 + a_row;
                uint32_t a[4];
                ldsm4(a, xs + (uint32_t)((rm * ROWPAD + kk + a_ke) * 2));
#pragma unroll
                for (int j = 0; j < 4; ++j)
                    MMAF16(d[mi][j], a[0], a[1], a[2], a[3], bf[j * 2], bf[j * 2 + 1]);
            }
        }
        __syncthreads();
        if (c + NBUF < NC && tid == 0) {
            MBAR_EXPECT(mb0 + buf * 8, 2 * TILE_B);
            CPBULK(tileX(buf), A + aBase + (size_t)(c + NBUF) * TILE_E, TILE_B, mb0 + buf * 8);
            CPBULK(tileW(buf), B + bBase + (size_t)(c + NBUF) * TILE_E, TILE_B, mb0 + buf * 8);
        }
    }

#pragma unroll
    for (int mi = 0; mi < 4; ++mi) {
#pragma unroll
        for (int j = 0; j < 4; ++j) {
            int r0 = m0 + mw * 64 + mi * 16 + rq;
            int n  = n0 + nw * 32 + j * 8 + cq;
            float b0 = bias[n], b1 = bias[n + 1];
#pragma unroll
            for (int h2 = 0; h2 < 2; ++h2) {
                int r = r0 + h2 * 8;
                float v0 = d[mi][j][h2 * 2 + 0] + b0;
                float v1 = d[mi][j][h2 * 2 + 1] + b1;
                if (mode == 0) {
                    float2 o; o.x = v0; o.y = v1;
                    *(float2*)(dst + (size_t)r * D + n) = o;
                } else {
                    v0 *= scale; v1 *= scale;
                    int b = r >> 11, srow = r & 2047;
                    int hh = n >> 6, dd = n & 63;
                    int bh = b * H + hh;
                    size_t base;
                    if (mode == 1)
                        base = ((size_t)bh * (S / 128) + (srow >> 7)) * QTILE_E
                             + (srow & 127) * RP + dd;
                    else
                        base = ((size_t)bh * (S / 64) + (srow >> 6)) * KVTILE_E
                             + (srow & 63) * RP + dd;
                    __half2 hp;
                    hp.x = __float2half_rn(v0);
                    hp.y = __float2half_rn(v1);
                    *(uint32_t*)(dsth + base) = h2u(hp);
                }
            }
        }
    }
}

__global__ void __launch_bounds__(256, 2) gemm_qkv_kernel(
    const float* __restrict__ bq, const float* __restrict__ bk,
    const float* __restrict__ bv)
{
    const int z = blockIdx.z;
    const float* bias = (z == 0) ? bq : (z == 1 ? bk : bv);
    __half* dh = (z == 0) ? g_q : (z == 1 ? g_k : g_v);
    float scale = (z == 0) ? SCALE : 1.0f;
    gemm_core(g_x[z], g_w[z], bias, nullptr, dh, scale, (z == 0) ? 1 : 2);
}

__global__ void __launch_bounds__(256, 2) gemm_out_kernel(
    const float* __restrict__ bo, float* __restrict__ out)
{
    gemm_core(g_a, g_w[3], bo, out, nullptr, 1.0f, 0);
}

// ---------------------------------------------------------------------------
// Flash attention, f16 single-term, QT=128, KT=64, 8 warps, 2 CTAs/SM.
// ---------------------------------------------------------------------------
__global__ void __launch_bounds__(256, 2) flash_kernel(const float* __restrict__ prev)
{
    extern __shared__ char sm[];
    const uint32_t sb  = smem_u32(sm);
    const uint32_t mb0 = sb + FL_MBAR;

    const int tid  = threadIdx.x;
    const int lane = tid & 31;
    const int w    = tid >> 5;
    const int bh   = blockIdx.y;
    const int b    = bh >> 4;
    const int hq   = bh & 15;
    const int q0   = blockIdx.x * QT;
    const int rq   = lane >> 2;
    const int cq   = (lane & 3) * 2;
    const int mrow = w * 16;

    const __half* Qt = g_q + ((size_t)bh * (S / 128) + blockIdx.x) * QTILE_E;
    const __half* Kt = g_k + (size_t)bh * (S / 64) * KVTILE_E;
    const __half* Vt = g_v + (size_t)bh * (S / 64) * KVTILE_E;
    const unsigned char* mkg = g_maskb + b * S;

    if (tid == 0) {
        MBAR_INIT(mb0, 1);
        MBAR_INIT(mb0 + 8, 1);
    }
    __syncthreads();
    if (tid == 0) {
        MBAR_EXPECT(mb0, QBYTES + 2 * KVBYTES + 64);
        CPBULK(sb + OFF_Q, Qt, QBYTES, mb0);
        CPBULK(sb + OFF_KV + 0 * KVBUF + 0 * KVBYTES, Kt, KVBYTES, mb0);
        CPBULK(sb + OFF_KV + 0 * KVBUF + 1 * KVBYTES, Vt, KVBYTES, mb0);
        CPBULK(sb + OFF_MK, mkg, 64, mb0);
        MBAR_EXPECT(mb0 + 8, 2 * KVBYTES + 64);
        CPBULK(sb + OFF_KV + 1 * KVBUF + 0 * KVBYTES, Kt + KVTILE_E, KVBYTES, mb0 + 8);
        CPBULK(sb + OFF_KV + 1 * KVBUF + 1 * KVBYTES, Vt + KVTILE_E, KVBYTES, mb0 + 8);
        CPBULK(sb + OFF_MK + 64, mkg + 64, 64, mb0 + 8);
    }

    float m_i[2] = {-3.0e38f, -3.0e38f};
    float l_i[2] = {0.f, 0.f};
    float o[8][4];
#pragma unroll
    for (int j = 0; j < 8; ++j)
#pragma unroll
        for (int r = 0; r < 4; ++r) o[j][r] = 0.f;

    const float* prow0 = prev + ((size_t)bh * S + q0 + mrow + rq) * S;
    const float* prow1 = prow0 + (size_t)8 * S;

    for (int t = 0; t < NT; ++t) {
        const int buf = t & 1;
        mbar_wait(mb0 + buf * 8, (uint32_t)((t >> 1) & 1));

        const uint32_t KS = sb + OFF_KV + buf * KVBUF;
        const uint32_t VS = KS + KVBYTES;
        const uint32_t QS = sb + OFF_Q;

        // --- QK^T (single term) ---
        float s[8][4];
#pragma unroll
        for (int j = 0; j < 8; ++j)
#pragma unroll
            for (int r = 0; r < 4; ++r) s[j][r] = 0.f;

#pragma unroll
        for (int kc = 0; kc < 4; ++kc) {
            uint32_t aoff = (uint32_t)((mrow + (lane & 15)) * (RP * 2)
                                       + kc * 32 + (lane >> 4) * 16);
            uint32_t a[4];
            ldsm4(a, QS + aoff);
#pragma unroll
            for (int jp = 0; jp < 4; ++jp) {
                uint32_t boff = (uint32_t)(((jp * 2 + (lane >> 4)) * 8 + (lane & 7)) * (RP * 2)
                                           + kc * 32 + ((lane >> 3) & 1) * 16);
                uint32_t bf[4];
                ldsm4(bf, KS + boff);
                MMAF16(s[2 * jp],     a[0], a[1], a[2], a[3], bf[0], bf[1]);
                MMAF16(s[2 * jp + 1], a[0], a[1], a[2], a[3], bf[2], bf[3]);
            }
        }

        // --- + prev, mask ---
#pragma unroll
        for (int j = 0; j < 8; ++j) {
            const unsigned char* mkp = (const unsigned char*)(sm + OFF_MK + buf * 64 + j * 8 + cq);
            unsigned char mk0 = mkp[0], mk1 = mkp[1];
            float2 p0 = *(const float2*)(prow0 + (size_t)t * KT + j * 8 + cq);
            float2 p1 = *(const float2*)(prow1 + (size_t)t * KT + j * 8 + cq);
            s[j][0] = mk0 ? -1.0e30f : s[j][0] + p0.x;
            s[j][1] = mk1 ? -1.0e30f : s[j][1] + p0.y;
            s[j][2] = mk0 ? -1.0e30f : s[j][2] + p1.x;
            s[j][3] = mk1 ? -1.0e30f : s[j][3] + p1.y;
        }

        // --- online softmax (rows rq, rq+8) ---
#pragma unroll
        for (int r = 0; r < 2; ++r) {
            float mx = -3.0e38f;
#pragma unroll
            for (int j = 0; j < 8; ++j)
                mx = fmaxf(mx, fmaxf(s[j][2 * r], s[j][2 * r + 1]));
            mx = fmaxf(mx, __shfl_xor_sync(0xffffffffu, mx, 1));
            mx = fmaxf(mx, __shfl_xor_sync(0xffffffffu, mx, 2));
            float m_new = fmaxf(m_i[r], mx);
            float corr  = __expf(m_i[r] - m_new);
            float rs = 0.f;
#pragma unroll
            for (int j = 0; j < 8; ++j) {
                s[j][2 * r]     = __expf(s[j][2 * r]     - m_new);
                s[j][2 * r + 1] = __expf(s[j][2 * r + 1] - m_new);
                rs += s[j][2 * r] + s[j][2 * r + 1];
            }
            rs += __shfl_xor_sync(0xffffffffu, rs, 1);
            rs += __shfl_xor_sync(0xffffffffu, rs, 2);
            l_i[r] = l_i[r] * corr + rs;
            m_i[r] = m_new;
#pragma unroll
            for (int j = 0; j < 8; ++j) {
                o[j][2 * r]     *= corr;
                o[j][2 * r + 1] *= corr;
            }
        }

        // --- P@V (single term), P from registers ---
#pragma unroll
        for (int kc2 = 0; kc2 < 4; ++kc2) {
            const int j0 = 2 * kc2, j1 = j0 + 1;
            uint32_t pa[4];
#pragma unroll
            for (int q = 0; q < 4; ++q) {
                const int jt = (q & 2) ? j1 : j0;
                const int rr = (q & 1) ? 2 : 0;
                __half2 hp;
                hp.x = __float2half_rn(s[jt][rr]);
                hp.y = __float2half_rn(s[jt][rr + 1]);
                pa[q] = h2u(hp);
            }
#pragma unroll
            for (int jp = 0; jp < 4; ++jp) {
                uint32_t voff = (uint32_t)((kc2 * 16 + ((lane >> 3) & 1) * 8 + (lane & 7)) * (RP * 2)
                                           + (jp * 2 + (lane >> 4)) * 16);
                uint32_t vf[4];
                ldsm4t(vf, VS + voff);
                MMAF16(o[2 * jp],     pa[0], pa[1], pa[2], pa[3], vf[0], vf[1]);
                MMAF16(o[2 * jp + 1], pa[0], pa[1], pa[2], pa[3], vf[2], vf[3]);
            }
        }

        __syncthreads();
        if (t + 2 < NT && tid == 0) {
            MBAR_EXPECT(mb0 + buf * 8, 2 * KVBYTES + 64);
            CPBULK(sb + OFF_KV + buf * KVBUF + 0 * KVBYTES, Kt + (size_t)(t + 2) * KVTILE_E, KVBYTES, mb0 + buf * 8);
            CPBULK(sb + OFF_KV + buf * KVBUF + 1 * KVBYTES, Vt + (size_t)(t + 2) * KVTILE_E, KVBYTES, mb0 + buf * 8);
            CPBULK(sb + OFF_MK + buf * 64, mkg + (size_t)(t + 2) * 64, 64, mb0 + buf * 8);
        }
    }

    // --- epilogue: normalize, emit f16 attn into GEMM-tiled layout ---
    const float inv0 = 1.0f / fmaxf(l_i[0], 1e-30f);
    const float inv1 = 1.0f / fmaxf(l_i[1], 1e-30f);
    const size_t mrow0 = (size_t)b * S + q0 + mrow + rq;
#pragma unroll
    for (int jn = 0; jn < 8; ++jn) {
        const int col = hq * 64 + jn * 8 + cq;
        float v0 = o[jn][0] * inv0, v1 = o[jn][1] * inv0;
        float v2 = o[jn][2] * inv1, v3 = o[jn][3] * inv1;
#pragma unroll
        for (int h2 = 0; h2 < 2; ++h2) {
            size_t m = mrow0 + h2 * 8;
            float x = h2 ? v2 : v0, y = h2 ? v3 : v1;
            size_t off = ((m >> 7) * (size_t)NC + (col >> 5)) * TILE_E
                       + (m & 127) * ROWPAD + (col & 31);
            __half2 hp;
            hp.x = __float2half_rn(x);
            hp.y = __float2half_rn(y);
            *(uint32_t*)(g_a + off) = h2u(hp);
        }
    }
}

// ---------------------------------------------------------------------------
// Inputs: 0:q 1:k 2:v 3:prev 4:mask 5:Wq 6:bq 7:Wk 8:bk 9:Wv 10:bv 11:Wo 12:bo
// ---------------------------------------------------------------------------
extern "C" void kernel_launch(void* const* d_in, const int* in_sizes, int n_in,
                              void* d_out, int out_size)
{
    (void)in_sizes; (void)n_in; (void)out_size;

    const float* q    = (const float*)d_in[0];
    const float* kk   = (const float*)d_in[1];
    const float* v    = (const float*)d_in[2];
    const float* prev = (const float*)d_in[3];
    const unsigned char* mask = (const unsigned char*)d_in[4];
    const float* Wq = (const float*)d_in[5];
    const float* bq = (const float*)d_in[6];
    const float* Wk = (const float*)d_in[7];
    const float* bk = (const float*)d_in[8];
    const float* Wv = (const float*)d_in[9];
    const float* bv = (const float*)d_in[10];
    const float* Wo = (const float*)d_in[11];
    const float* bo = (const float*)d_in[12];
    float* out = (float*)d_out;

    cudaFuncSetAttribute(gemm_qkv_kernel,
                         cudaFuncAttributeMaxDynamicSharedMemorySize, SMEM_GEMM);
    cudaFuncSetAttribute(gemm_out_kernel,
                         cudaFuncAttributeMaxDynamicSharedMemorySize, SMEM_GEMM);
    cudaFuncSetAttribute(flash_kernel,
                         cudaFuncAttributeMaxDynamicSharedMemorySize, SMEM_FLASH);

    mask_prepare_kernel<<<1, 256>>>(mask);

    const int nX = M * D, nW = D * D;
    conv_x_kernel<<<dim3(nX / 8 / 256, 1, 3), 256>>>(q, kk, v);
    conv_w_kernel<<<dim3(nW / 8 / 256, 1, 4), 256>>>(Wq, Wk, Wv, Wo);

    gemm_qkv_kernel<<<dim3(D / BN, M / BM, 3), 256, SMEM_GEMM>>>(bq, bk, bv);
    flash_kernel<<<dim3(S / QT, Bb * H), 256, SMEM_FLASH>>>(prev);
    gemm_out_kernel<<<dim3(D / BN, M / BM), 256, SMEM_GEMM>>>(bo, out);
}